// round 12
// baseline (speedup 1.0000x reference)
#include <cuda_runtime.h>

// ---------------------------------------------------------------------------
// MPNN forward, fp32, graph-capturable, allocation-free.
// R12: R11 (EQ=8 edge-pair FFMA2, 14 warps) with input operands loaded as
// ulonglong2 (LDS.128 broadcast) — halves smem-crossbar broadcast slots,
// flipping the edge kernel from crossbar-bound to fma-bound.
// GRU = R5 f32x2 version.
// ---------------------------------------------------------------------------

#define N_NODES 50000
#define N_EDGES 800000
#define NODE_DIM 32
#define EDGE_DIM 16
#define HID 64
#define MSG_HID 128
#define NUM_GRAPHS 512
#define NUM_MP 3
#define S2S_STEPS 6
#define IN_DIM (2 * HID + EDGE_DIM)  // 144

// ------------------------- scratch (device globals) ------------------------
__device__ float g_x[N_NODES * HID];
__device__ float g_m[N_NODES * HID];
__device__ float g_qh[NUM_GRAPHS * HID];
__device__ float g_qc[NUM_GRAPHS * HID];
__device__ float g_qstar[NUM_GRAPHS * 2 * HID];
__device__ float g_e[N_NODES];
__device__ float g_a[N_NODES];
__device__ unsigned g_emax[NUM_GRAPHS];
__device__ float g_asum[NUM_GRAPHS];
__device__ float g_rvec[NUM_GRAPHS * HID];

__device__ __forceinline__ float sigmoidf_(float x) { return 1.f / (1.f + expf(-x)); }

__device__ __forceinline__ unsigned enc_f(float f) {
    unsigned u = __float_as_uint(f);
    return (u & 0x80000000u) ? ~u : (u | 0x80000000u);
}
__device__ __forceinline__ float dec_f(unsigned k) {
    return (k & 0x80000000u) ? __uint_as_float(k & 0x7fffffffu)
                             : __uint_as_float(~k);
}

// ----------------------- packed f32x2 helpers (sm_100+) --------------------
__device__ __forceinline__ unsigned long long fma2(unsigned long long a,
                                                   unsigned long long b,
                                                   unsigned long long c) {
    unsigned long long d;
    asm("fma.rn.f32x2 %0, %1, %2, %3;" : "=l"(d) : "l"(a), "l"(b), "l"(c));
    return d;
}
__device__ __forceinline__ unsigned long long dup2(float x) {
    unsigned long long d;
    asm("mov.b64 %0, {%1, %1};" : "=l"(d) : "f"(x));
    return d;
}
__device__ __forceinline__ float2 unpk(unsigned long long v) {
    float lo, hi;
    asm("mov.b64 {%0, %1}, %2;" : "=f"(lo), "=f"(hi) : "l"(v));
    return make_float2(lo, hi);
}
__device__ __forceinline__ unsigned long long ld2u(const float* p) {
    return *(const unsigned long long*)p;
}

// ------------------------------ zero kernels -------------------------------
__global__ void zero_m_kernel() {
    int t = blockIdx.x * blockDim.x + threadIdx.x;
    if (t < N_NODES * HID) g_m[t] = 0.f;
}
__global__ void zero_s2s_state_kernel() {
    int t = blockIdx.x * blockDim.x + threadIdx.x;
    if (t < NUM_GRAPHS * HID) { g_qh[t] = 0.f; g_qc[t] = 0.f; }
    if (t < NUM_GRAPHS * 2 * HID) g_qstar[t] = 0.f;
}
__global__ void zero_attn_kernel() {
    int t = blockIdx.x * blockDim.x + threadIdx.x;
    if (t < NUM_GRAPHS) { g_emax[t] = 0u; g_asum[t] = 0.f; }
    if (t < NUM_GRAPHS * HID) g_rvec[t] = 0.f;
}

// ------------------------------- embedding ---------------------------------
__global__ void embed_kernel(const float* __restrict__ xf,
                             const float* __restrict__ W,
                             const float* __restrict__ b) {
    int t = blockIdx.x * blockDim.x + threadIdx.x;
    if (t >= N_NODES * HID) return;
    int v = t >> 6, o = t & 63;
    const float* xr = xf + v * NODE_DIM;
    float acc = b[o];
#pragma unroll
    for (int c = 0; c < NODE_DIM; c++) acc += xr[c] * W[c * HID + o];
    g_x[t] = acc;
}

// ------------------------- edge message MLP kernel -------------------------
// 14 warps, EQ=8 edges/warp. Staging channel-major, stride 8 floats:
//   win[idx*8 + k] = feature idx of edge k. A single LDS.128 broadcast
//   (ulonglong2) yields TWO edge-pair f32x2 operands.
#define EK_THREADS 448
#define EK_WARPS 14
#define EQ 8
#define WIN_F (IN_DIM * EQ)    // 1152
#define WHID_F (MSG_HID * EQ)  // 1024
#define EK_SMEM_FLOATS (IN_DIM * MSG_HID + MSG_HID + MSG_HID * HID + HID + \
                        EK_WARPS * (WIN_F + WHID_F))

__global__ __launch_bounds__(EK_THREADS, 1)
void edge_msg_kernel(const int* __restrict__ ei, const float* __restrict__ ea,
                     const float* __restrict__ W1, const float* __restrict__ b1,
                     const float* __restrict__ W2, const float* __restrict__ b2) {
    extern __shared__ float smem[];
    float* W1s  = smem;                              // 144*128 row-major
    float* b1s  = W1s + IN_DIM * MSG_HID;            // 128
    float* W2s  = b1s + MSG_HID;                     // 128*64 row-major
    float* b2s  = W2s + MSG_HID * HID;               // 64
    float* win_all  = b2s + HID;                     // warps * 1152
    float* whid_all = win_all + EK_WARPS * WIN_F;    // warps * 1024

    int tid = threadIdx.x;
    for (int i = tid; i < IN_DIM * MSG_HID / 4; i += EK_THREADS)
        ((float4*)W1s)[i] = ((const float4*)W1)[i];
    for (int i = tid; i < MSG_HID; i += EK_THREADS) b1s[i] = b1[i];
    for (int i = tid; i < MSG_HID * HID / 4; i += EK_THREADS)
        ((float4*)W2s)[i] = ((const float4*)W2)[i];
    for (int i = tid; i < HID; i += EK_THREADS) b2s[i] = b2[i];
    __syncthreads();

    int warp = tid >> 5, lane = tid & 31;
    float* win  = win_all + warp * WIN_F;
    float* whid = whid_all + warp * WHID_F;
    const int* src = ei;
    const int* dst = ei + N_EDGES;

    const int noct = N_EDGES / EQ;  // 100000
    for (int q = blockIdx.x * EK_WARPS + warp; q < noct;
         q += gridDim.x * EK_WARPS) {
        int e0 = q * EQ;
        int d[EQ], s_[EQ];
#pragma unroll
        for (int k = 0; k < EQ; k++) {
            s_[k] = __ldg(src + e0 + k);
            d[k]  = __ldg(dst + e0 + k);
        }
        // stage channel-major: win[idx*8 + k]
#pragma unroll
        for (int j = 0; j < 5; j++) {
            int idx = lane + 32 * j;
            if (idx < IN_DIM) {
                float v[EQ];
#pragma unroll
                for (int k = 0; k < EQ; k++) {
                    if (j < 2) v[k] = g_x[d[k] * HID + idx];
                    else if (j < 4) v[k] = g_x[s_[k] * HID + (idx - HID)];
                    else v[k] = __ldg(ea + (e0 + k) * EDGE_DIM + (idx - 2 * HID));
                }
                float* base = win + idx * EQ;
                *(float4*)base = make_float4(v[0], v[1], v[2], v[3]);
                *(float4*)(base + 4) = make_float4(v[4], v[5], v[6], v[7]);
            }
        }
        __syncwarp();

        // ---- layer 1: lane computes channels {lane,+32,+64,+96} for 8
        // edges (4 edge-pairs). Inputs: 2 LDS.128 broadcasts per i.
        unsigned long long acc[4][4];  // [out j][pair p]
#pragma unroll
        for (int j = 0; j < 4; j++)
#pragma unroll
            for (int p = 0; p < 4; p++) acc[j][p] = 0ull;

#pragma unroll 2
        for (int i = 0; i < IN_DIM; i++) {
            const float* wr = W1s + i * MSG_HID + lane;
            unsigned long long w0 = dup2(wr[0]);
            unsigned long long w1 = dup2(wr[32]);
            unsigned long long w2 = dup2(wr[64]);
            unsigned long long w3 = dup2(wr[96]);
            const ulonglong2* bp = (const ulonglong2*)(win + i * EQ);
            ulonglong2 inA = bp[0];   // pairs 0,1
            ulonglong2 inB = bp[1];   // pairs 2,3
            acc[0][0] = fma2(w0, inA.x, acc[0][0]);
            acc[0][1] = fma2(w0, inA.y, acc[0][1]);
            acc[0][2] = fma2(w0, inB.x, acc[0][2]);
            acc[0][3] = fma2(w0, inB.y, acc[0][3]);
            acc[1][0] = fma2(w1, inA.x, acc[1][0]);
            acc[1][1] = fma2(w1, inA.y, acc[1][1]);
            acc[1][2] = fma2(w1, inB.x, acc[1][2]);
            acc[1][3] = fma2(w1, inB.y, acc[1][3]);
            acc[2][0] = fma2(w2, inA.x, acc[2][0]);
            acc[2][1] = fma2(w2, inA.y, acc[2][1]);
            acc[2][2] = fma2(w2, inB.x, acc[2][2]);
            acc[2][3] = fma2(w2, inB.y, acc[2][3]);
            acc[3][0] = fma2(w3, inA.x, acc[3][0]);
            acc[3][1] = fma2(w3, inA.y, acc[3][1]);
            acc[3][2] = fma2(w3, inB.x, acc[3][2]);
            acc[3][3] = fma2(w3, inB.y, acc[3][3]);
        }
        // bias + relu; store channel-major stride 8
#pragma unroll
        for (int j = 0; j < 4; j++) {
            int ch = lane + 32 * j;
            float b = b1s[ch];
            float2 f0 = unpk(acc[j][0]);
            float2 f1 = unpk(acc[j][1]);
            float2 f2 = unpk(acc[j][2]);
            float2 f3 = unpk(acc[j][3]);
            float* hb = whid + ch * EQ;
            *(float4*)hb = make_float4(fmaxf(f0.x + b, 0.f), fmaxf(f0.y + b, 0.f),
                                       fmaxf(f1.x + b, 0.f), fmaxf(f1.y + b, 0.f));
            *(float4*)(hb + 4) = make_float4(fmaxf(f2.x + b, 0.f), fmaxf(f2.y + b, 0.f),
                                             fmaxf(f3.x + b, 0.f), fmaxf(f3.y + b, 0.f));
        }
        __syncwarp();

        // ---- layer 2: lane computes channels {lane, lane+32} ----
        unsigned long long acc2[2][4];
#pragma unroll
        for (int j = 0; j < 2; j++)
#pragma unroll
            for (int p = 0; p < 4; p++) acc2[j][p] = 0ull;
#pragma unroll 2
        for (int i = 0; i < MSG_HID; i++) {
            const float* wr = W2s + i * HID + lane;
            unsigned long long w0 = dup2(wr[0]);
            unsigned long long w1 = dup2(wr[32]);
            const ulonglong2* bp = (const ulonglong2*)(whid + i * EQ);
            ulonglong2 hA = bp[0];
            ulonglong2 hB = bp[1];
            acc2[0][0] = fma2(w0, hA.x, acc2[0][0]);
            acc2[0][1] = fma2(w0, hA.y, acc2[0][1]);
            acc2[0][2] = fma2(w0, hB.x, acc2[0][2]);
            acc2[0][3] = fma2(w0, hB.y, acc2[0][3]);
            acc2[1][0] = fma2(w1, hA.x, acc2[1][0]);
            acc2[1][1] = fma2(w1, hA.y, acc2[1][1]);
            acc2[1][2] = fma2(w1, hB.x, acc2[1][2]);
            acc2[1][3] = fma2(w1, hB.y, acc2[1][3]);
        }
#pragma unroll
        for (int j = 0; j < 2; j++) {
            int ch = lane + 32 * j;
            float b = b2s[ch];
#pragma unroll
            for (int p = 0; p < 4; p++) {
                float2 f = unpk(acc2[j][p]);
                atomicAdd(&g_m[d[2 * p] * HID + ch], f.x + b);
                atomicAdd(&g_m[d[2 * p + 1] * HID + ch], f.y + b);
            }
        }
        __syncwarp();
    }
}

// --------------------------------- GRU -------------------------------------
#define GK_THREADS 256
#define GK_WARPS 8
#define NPW 4
#define GRU_SMEM_F (64 * 96 * 2 * 2 + 384 + GK_WARPS * NPW * 128 * 2)

__global__ __launch_bounds__(GK_THREADS, 1)
void gru_kernel(const float* __restrict__ Wih, const float* __restrict__ Whh,
                const float* __restrict__ bih, const float* __restrict__ bhh) {
    extern __shared__ float s[];
    float2* WihT2 = (float2*)s;                 // [c(64)][p(96)]
    float2* WhhT2 = WihT2 + 64 * 96;
    float* bihs = (float*)(WhhT2 + 64 * 96);    // 192
    float* bhhs = bihs + 192;                   // 192
    float2* stg = (float2*)(bhhs + 192);        // [warp][NPW][128] dup (m|h)

    int tid = threadIdx.x;
    for (int idx = tid; idx < 64 * 96; idx += GK_THREADS) {
        int c = idx / 96, p = idx % 96;
        WihT2[c * 96 + p] = make_float2(Wih[(2 * p) * HID + c],
                                        Wih[(2 * p + 1) * HID + c]);
        WhhT2[c * 96 + p] = make_float2(Whh[(2 * p) * HID + c],
                                        Whh[(2 * p + 1) * HID + c]);
    }
    for (int idx = tid; idx < 192; idx += GK_THREADS) {
        bihs[idx] = bih[idx];
        bhhs[idx] = bhh[idx];
    }
    __syncthreads();

    int warp = tid >> 5, lane = tid & 31;
    float2* ws = stg + warp * NPW * 128;
    const int ngroups = N_NODES / NPW;  // 12500

    for (int g = blockIdx.x * GK_WARPS + warp; g < ngroups;
         g += gridDim.x * GK_WARPS) {
        int v0 = g * NPW;
#pragma unroll
        for (int n = 0; n < NPW; n++) {
            int v = v0 + n;
            float m0 = g_m[v * HID + lane];
            float m1 = g_m[v * HID + lane + 32];
            float h0 = g_x[v * HID + lane];
            float h1 = g_x[v * HID + lane + 32];
            ws[n * 128 + lane] = make_float2(m0, m0);
            ws[n * 128 + lane + 32] = make_float2(m1, m1);
            ws[n * 128 + 64 + lane] = make_float2(h0, h0);
            ws[n * 128 + 64 + lane + 32] = make_float2(h1, h1);
        }
        __syncwarp();

        unsigned long long ai[NPW][3], ah[NPW][3];
#pragma unroll
        for (int n = 0; n < NPW; n++)
#pragma unroll
            for (int j = 0; j < 3; j++) { ai[n][j] = 0ull; ah[n][j] = 0ull; }

#pragma unroll 2
        for (int c = 0; c < HID; c++) {
            unsigned long long wi0 = ld2u((const float*)(WihT2 + c * 96 + lane));
            unsigned long long wi1 = ld2u((const float*)(WihT2 + c * 96 + lane + 32));
            unsigned long long wi2 = ld2u((const float*)(WihT2 + c * 96 + lane + 64));
            unsigned long long wh0 = ld2u((const float*)(WhhT2 + c * 96 + lane));
            unsigned long long wh1 = ld2u((const float*)(WhhT2 + c * 96 + lane + 32));
            unsigned long long wh2 = ld2u((const float*)(WhhT2 + c * 96 + lane + 64));
#pragma unroll
            for (int n = 0; n < NPW; n++) {
                unsigned long long mv = ld2u((const float*)(ws + n * 128 + c));
                unsigned long long hv = ld2u((const float*)(ws + n * 128 + 64 + c));
                ai[n][0] = fma2(wi0, mv, ai[n][0]);
                ai[n][1] = fma2(wi1, mv, ai[n][1]);
                ai[n][2] = fma2(wi2, mv, ai[n][2]);
                ah[n][0] = fma2(wh0, hv, ah[n][0]);
                ah[n][1] = fma2(wh1, hv, ah[n][1]);
                ah[n][2] = fma2(wh2, hv, ah[n][2]);
            }
        }

        int u0 = 2 * lane;
#pragma unroll
        for (int n = 0; n < NPW; n++) {
            int v = v0 + n;
            float2 ir = unpk(ai[n][0]), hr = unpk(ah[n][0]);
            float2 iz = unpk(ai[n][1]), hz = unpk(ah[n][1]);
            float2 in_ = unpk(ai[n][2]), hn = unpk(ah[n][2]);
            float holdA = ws[n * 128 + 64 + u0].x;
            float holdB = ws[n * 128 + 64 + u0 + 1].x;
            float rA = sigmoidf_(ir.x + bihs[u0] + hr.x + bhhs[u0]);
            float rB = sigmoidf_(ir.y + bihs[u0 + 1] + hr.y + bhhs[u0 + 1]);
            float zA = sigmoidf_(iz.x + bihs[64 + u0] + hz.x + bhhs[64 + u0]);
            float zB = sigmoidf_(iz.y + bihs[64 + u0 + 1] + hz.y + bhhs[64 + u0 + 1]);
            float nA = tanhf(in_.x + bihs[128 + u0] + rA * (hn.x + bhhs[128 + u0]));
            float nB = tanhf(in_.y + bihs[128 + u0 + 1] + rB * (hn.y + bhhs[128 + u0 + 1]));
            float oA = (1.f - zA) * nA + zA * holdA;
            float oB = (1.f - zB) * nB + zB * holdB;
            *(float2*)(g_x + v * HID + u0) = make_float2(oA, oB);
        }
        __syncwarp();
    }
}

// ------------------------------- LSTM cell ---------------------------------
#define LSTM_SMEM_F (256 * 128 + 256 * 64 + 4 * 128 + 4 * 64)

__global__ __launch_bounds__(256, 1)
void lstm_kernel(const float* __restrict__ Wih, const float* __restrict__ Whh,
                 const float* __restrict__ bih, const float* __restrict__ bhh) {
    extern __shared__ float s[];
    float* WihT = s;                   // [c(128)][gate(256)]
    float* WhhT = WihT + 256 * 128;    // [c(64)][gate(256)]
    float* qs_s = WhhT + 256 * 64;     // [4][128]
    float* qh_s = qs_s + 4 * 128;      // [4][64]

    int tid = threadIdx.x;
    for (int idx = tid; idx < 256 * 128; idx += 256) {
        int g = idx >> 7, c = idx & 127;
        WihT[c * 256 + g] = Wih[idx];
    }
    for (int idx = tid; idx < 256 * 64; idx += 256) {
        int g = idx >> 6, c = idx & 63;
        WhhT[c * 256 + g] = Whh[idx];
    }
    int g0 = blockIdx.x * 4;
    for (int idx = tid; idx < 4 * 128; idx += 256)
        qs_s[idx] = g_qstar[g0 * 128 + idx];
    for (int idx = tid; idx < 4 * 64; idx += 256)
        qh_s[idx] = g_qh[g0 * 64 + idx];
    __syncthreads();

    int lg = tid >> 6;
    int u = tid & 63;
    int g = g0 + lg;
    float accI = bih[u] + bhh[u];
    float accF = bih[64 + u] + bhh[64 + u];
    float accG = bih[128 + u] + bhh[128 + u];
    float accO = bih[192 + u] + bhh[192 + u];
    const float* qs = qs_s + lg * 128;
#pragma unroll 4
    for (int c = 0; c < 128; c++) {
        float v = qs[c];
        const float* w = &WihT[c * 256];
        accI += v * w[u];
        accF += v * w[64 + u];
        accG += v * w[128 + u];
        accO += v * w[192 + u];
    }
    const float* qh = qh_s + lg * 64;
#pragma unroll 4
    for (int c = 0; c < 64; c++) {
        float v = qh[c];
        const float* w = &WhhT[c * 256];
        accI += v * w[u];
        accF += v * w[64 + u];
        accG += v * w[128 + u];
        accO += v * w[192 + u];
    }
    float i_ = sigmoidf_(accI), f_ = sigmoidf_(accF);
    float gg = tanhf(accG), o_ = sigmoidf_(accO);
    float c_new = f_ * g_qc[g * 64 + u] + i_ * gg;
    float h_new = o_ * tanhf(c_new);
    g_qc[g * 64 + u] = c_new;
    g_qh[g * 64 + u] = h_new;
}

// ----------------------------- attention steps -----------------------------
__global__ void attn_dot_kernel(const int* __restrict__ batch) {
    int wg = (blockIdx.x * blockDim.x + threadIdx.x) >> 5;
    int lane = threadIdx.x & 31;
    if (wg >= N_NODES) return;
    int v = wg;
    int b = batch[v];
    float p = g_x[v * HID + lane] * g_qh[b * HID + lane] +
              g_x[v * HID + lane + 32] * g_qh[b * HID + lane + 32];
#pragma unroll
    for (int o = 16; o; o >>= 1) p += __shfl_down_sync(0xffffffffu, p, o);
    if (lane == 0) {
        g_e[v] = p;
        atomicMax(&g_emax[b], enc_f(p));
    }
}

__global__ void attn_exp_kernel(const int* __restrict__ batch) {
    int v = blockIdx.x * blockDim.x + threadIdx.x;
    if (v >= N_NODES) return;
    int b = batch[v];
    float a = expf(g_e[v] - dec_f(g_emax[b]));
    g_a[v] = a;
    atomicAdd(&g_asum[b], a);
}

__global__ void attn_rvec_kernel(const int* __restrict__ batch) {
    int wg = (blockIdx.x * blockDim.x + threadIdx.x) >> 5;
    int lane = threadIdx.x & 31;
    if (wg >= N_NODES) return;
    int v = wg;
    int b = batch[v];
    float coef = g_a[v] / g_asum[b];
    atomicAdd(&g_rvec[b * HID + lane], coef * g_x[v * HID + lane]);
    atomicAdd(&g_rvec[b * HID + lane + 32], coef * g_x[v * HID + lane + 32]);
}

__global__ void qstar_kernel() {
    int t = blockIdx.x * blockDim.x + threadIdx.x;
    if (t >= NUM_GRAPHS * HID) return;
    int g = t >> 6, u = t & 63;
    g_qstar[g * 2 * HID + u] = g_qh[t];
    g_qstar[g * 2 * HID + HID + u] = g_rvec[t];
}

// ------------------------------- regressor ---------------------------------
__global__ void reg_kernel(const float* __restrict__ W1,
                           const float* __restrict__ b1,
                           const float* __restrict__ W2,
                           const float* __restrict__ b2,
                           float* __restrict__ out) {
    __shared__ float qs[128];
    __shared__ float red[64];
    int g = blockIdx.x;
    int u = threadIdx.x;  // 64 threads
    qs[u] = g_qstar[g * 128 + u];
    qs[u + 64] = g_qstar[g * 128 + u + 64];
    __syncthreads();
    float acc = b1[u];
#pragma unroll 4
    for (int c = 0; c < 128; c++) acc += qs[c] * W1[c * HID + u];
    red[u] = fmaxf(acc, 0.f) * W2[u];
    __syncthreads();
    for (int sft = 32; sft; sft >>= 1) {
        if (u < sft) red[u] += red[u + sft];
        __syncthreads();
    }
    if (u == 0) out[g] = red[0] + b2[0];
}

// ------------------------------ host driver --------------------------------
extern "C" void kernel_launch(void* const* d_in, const int* in_sizes, int n_in,
                              void* d_out, int out_size) {
    const float* x_feat     = (const float*)d_in[0];
    const int*   edge_index = (const int*)d_in[1];
    const float* edge_attr  = (const float*)d_in[2];
    const int*   batch      = (const int*)d_in[3];
    const float* W_emb = (const float*)d_in[4];
    const float* b_emb = (const float*)d_in[5];
    const float* W_m1  = (const float*)d_in[6];
    const float* b_m1  = (const float*)d_in[7];
    const float* W_m2  = (const float*)d_in[8];
    const float* b_m2  = (const float*)d_in[9];
    const float* gWih  = (const float*)d_in[10];
    const float* gWhh  = (const float*)d_in[11];
    const float* gbih  = (const float*)d_in[12];
    const float* gbhh  = (const float*)d_in[13];
    const float* lWih  = (const float*)d_in[14];
    const float* lWhh  = (const float*)d_in[15];
    const float* lbih  = (const float*)d_in[16];
    const float* lbhh  = (const float*)d_in[17];
    const float* Wr1   = (const float*)d_in[18];
    const float* br1   = (const float*)d_in[19];
    const float* Wr2   = (const float*)d_in[20];
    const float* br2   = (const float*)d_in[21];
    float* out = (float*)d_out;

    const int ek_smem   = EK_SMEM_FLOATS * (int)sizeof(float);
    const int gru_smem  = GRU_SMEM_F * (int)sizeof(float);
    const int lstm_smem = LSTM_SMEM_F * (int)sizeof(float);
    cudaFuncSetAttribute(edge_msg_kernel,
                         cudaFuncAttributeMaxDynamicSharedMemorySize, ek_smem);
    cudaFuncSetAttribute(gru_kernel,
                         cudaFuncAttributeMaxDynamicSharedMemorySize, gru_smem);
    cudaFuncSetAttribute(lstm_kernel,
                         cudaFuncAttributeMaxDynamicSharedMemorySize, lstm_smem);

    // 1. node embedding
    embed_kernel<<<(N_NODES * HID + 255) / 256, 256>>>(x_feat, W_emb, b_emb);

    // 2. message passing rounds
    for (int r = 0; r < NUM_MP; r++) {
        zero_m_kernel<<<(N_NODES * HID + 255) / 256, 256>>>();
        edge_msg_kernel<<<148, EK_THREADS, ek_smem>>>(edge_index, edge_attr,
                                                      W_m1, b_m1, W_m2, b_m2);
        gru_kernel<<<148, GK_THREADS, gru_smem>>>(gWih, gWhh, gbih, gbhh);
    }

    // 3. Set2Set
    zero_s2s_state_kernel<<<(NUM_GRAPHS * 2 * HID + 255) / 256, 256>>>();
    for (int s = 0; s < S2S_STEPS; s++) {
        lstm_kernel<<<NUM_GRAPHS / 4, 256, lstm_smem>>>(lWih, lWhh, lbih, lbhh);
        zero_attn_kernel<<<(NUM_GRAPHS * HID + 255) / 256, 256>>>();
        attn_dot_kernel<<<(N_NODES * 32 + 255) / 256, 256>>>(batch);
        attn_exp_kernel<<<(N_NODES + 255) / 256, 256>>>(batch);
        attn_rvec_kernel<<<(N_NODES * 32 + 255) / 256, 256>>>(batch);
        qstar_kernel<<<(NUM_GRAPHS * HID + 255) / 256, 256>>>();
    }

    // 4. regressor
    reg_kernel<<<NUM_GRAPHS, 64>>>(Wr1, br1, Wr2, br2, out);
    (void)in_sizes; (void)n_in; (void)out_size;
}

// round 14
// speedup vs baseline: 1.2835x; 1.2835x over previous
#include <cuda_runtime.h>
#include <cuda_bf16.h>
#include <cstdint>

// ---------------------------------------------------------------------------
// MPNN forward, graph-capturable, allocation-free.
// R14: edge MLP on mma.sync m16n8k16 bf16 (3-way split, fp32 accum) —
// baseline-ISA tensor cores (tcgen05 is blocked by the harness's compute_103
// virtual target). Layer-1 D fragments re-used register-local as layer-2 A
// fragments. GRU = f32x2 version; attention/Set2Set unchanged.
// ---------------------------------------------------------------------------

#define N_NODES 50000
#define N_EDGES 800000
#define NODE_DIM 32
#define EDGE_DIM 16
#define HID 64
#define MSG_HID 128
#define NUM_GRAPHS 512
#define NUM_MP 3
#define S2S_STEPS 6
#define IN_DIM (2 * HID + EDGE_DIM)  // 144

// ------------------------- scratch (device globals) ------------------------
__device__ __align__(16) float g_x[N_NODES * HID];
__device__ __align__(16) float g_m[N_NODES * HID];
__device__ float g_qh[NUM_GRAPHS * HID];
__device__ float g_qc[NUM_GRAPHS * HID];
__device__ float g_qstar[NUM_GRAPHS * 2 * HID];
__device__ float g_e[N_NODES];
__device__ float g_a[N_NODES];
__device__ unsigned g_emax[NUM_GRAPHS];
__device__ float g_asum[NUM_GRAPHS];
__device__ float g_rvec[NUM_GRAPHS * HID];

__device__ __forceinline__ float sigmoidf_(float x) { return 1.f / (1.f + expf(-x)); }

__device__ __forceinline__ unsigned enc_f(float f) {
    unsigned u = __float_as_uint(f);
    return (u & 0x80000000u) ? ~u : (u | 0x80000000u);
}
__device__ __forceinline__ float dec_f(unsigned k) {
    return (k & 0x80000000u) ? __uint_as_float(k & 0x7fffffffu)
                             : __uint_as_float(~k);
}

// ----------------------- packed f32x2 helpers (GRU) ------------------------
__device__ __forceinline__ unsigned long long fma2(unsigned long long a,
                                                   unsigned long long b,
                                                   unsigned long long c) {
    unsigned long long d;
    asm("fma.rn.f32x2 %0, %1, %2, %3;" : "=l"(d) : "l"(a), "l"(b), "l"(c));
    return d;
}
__device__ __forceinline__ float2 unpk(unsigned long long v) {
    float lo, hi;
    asm("mov.b64 {%0, %1}, %2;" : "=f"(lo), "=f"(hi) : "l"(v));
    return make_float2(lo, hi);
}
__device__ __forceinline__ unsigned long long ld2u(const float* p) {
    return *(const unsigned long long*)p;
}

// --------------------------- mma.sync primitives ---------------------------
// split fp32 pair (a=low element, b=high element) into hi/lo bf16x2
__device__ __forceinline__ void split2(float a, float b, uint32_t& hi, uint32_t& lo) {
    uint32_t h;
    asm("cvt.rn.bf16x2.f32 %0, %1, %2;" : "=r"(h) : "f"(b), "f"(a));  // low=a
    float ra = a - __uint_as_float(h << 16);
    float rb = b - __uint_as_float(h & 0xffff0000u);
    uint32_t l;
    asm("cvt.rn.bf16x2.f32 %0, %1, %2;" : "=r"(l) : "f"(rb), "f"(ra));
    hi = h; lo = l;
}

__device__ __forceinline__ void mma16816(float* c, const uint32_t* a,
                                         uint32_t b0, uint32_t b1) {
    asm volatile(
        "mma.sync.aligned.m16n8k16.row.col.f32.bf16.bf16.f32 "
        "{%0,%1,%2,%3}, {%4,%5,%6,%7}, {%8,%9}, {%0,%1,%2,%3};"
        : "+f"(c[0]), "+f"(c[1]), "+f"(c[2]), "+f"(c[3])
        : "r"(a[0]), "r"(a[1]), "r"(a[2]), "r"(a[3]), "r"(b0), "r"(b1));
}

// ------------------------------ zero kernels -------------------------------
__global__ void zero_m_kernel() {
    int t = blockIdx.x * blockDim.x + threadIdx.x;
    if (t < N_NODES * HID) g_m[t] = 0.f;
}
__global__ void zero_s2s_state_kernel() {
    int t = blockIdx.x * blockDim.x + threadIdx.x;
    if (t < NUM_GRAPHS * HID) { g_qh[t] = 0.f; g_qc[t] = 0.f; }
    if (t < NUM_GRAPHS * 2 * HID) g_qstar[t] = 0.f;
}
__global__ void zero_attn_kernel() {
    int t = blockIdx.x * blockDim.x + threadIdx.x;
    if (t < NUM_GRAPHS) { g_emax[t] = 0u; g_asum[t] = 0.f; }
    if (t < NUM_GRAPHS * HID) g_rvec[t] = 0.f;
}

// ------------------------------- embedding ---------------------------------
__global__ void embed_kernel(const float* __restrict__ xf,
                             const float* __restrict__ W,
                             const float* __restrict__ b) {
    int t = blockIdx.x * blockDim.x + threadIdx.x;
    if (t >= N_NODES * HID) return;
    int v = t >> 6, o = t & 63;
    const float* xr = xf + v * NODE_DIM;
    float acc = b[o];
#pragma unroll
    for (int c = 0; c < NODE_DIM; c++) acc += xr[c] * W[c * HID + o];
    g_x[t] = acc;
}

// ---------------------- edge message MLP on mma.sync -----------------------
// smem (bytes):
#define KP1 152   // padded K stride for W1T / A tiles (bank-safe)
#define KP2 136   // padded K stride for W2T
#define SW1H 0                          // [128][KP1] bf16  38912B
#define SW1L (SW1H + 128 * KP1 * 2)
#define SW2H (SW1L + 128 * KP1 * 2)     // [64][KP2] bf16   17408B
#define SW2L (SW2H + 64 * KP2 * 2)
#define SB1  (SW2L + 64 * KP2 * 2)      // 128 f32
#define SB2  (SB1 + 512)                // 64 f32
#define SA   (SB2 + 256)                // per-warp A hi+lo: [16][KP1] bf16 x2
#define SA_HALF (16 * KP1 * 2)          // 4864B
#define SA_WARP (2 * SA_HALF)           // 9728B
#define EK_WARPS 8
#define EK_SMEM_BYTES (SA + EK_WARPS * SA_WARP)   // 191232B

#define N_TILES (N_EDGES / 16)  // 50000

__global__ __launch_bounds__(256, 1)
void edge_msg_kernel(const int* __restrict__ ei, const float* __restrict__ ea,
                     const float* __restrict__ W1, const float* __restrict__ b1,
                     const float* __restrict__ W2, const float* __restrict__ b2) {
    extern __shared__ char sm[];
    int tid = threadIdx.x;
    int lane = tid & 31, wid = tid >> 5;

    // load + split + transpose weights: W1[k][n] -> W1T[n][k] hi/lo
    for (int idx = tid; idx < IN_DIM * MSG_HID; idx += 256) {
        int k = idx >> 7, n = idx & 127;
        float w = W1[idx];
        __nv_bfloat16 h = __float2bfloat16(w);
        float r = w - __bfloat162float(h);
        __nv_bfloat16 l = __float2bfloat16(r);
        ((__nv_bfloat16*)(sm + SW1H))[n * KP1 + k] = h;
        ((__nv_bfloat16*)(sm + SW1L))[n * KP1 + k] = l;
    }
    for (int idx = tid; idx < MSG_HID * HID; idx += 256) {
        int k = idx >> 6, n = idx & 63;
        float w = W2[idx];
        __nv_bfloat16 h = __float2bfloat16(w);
        float r = w - __bfloat162float(h);
        __nv_bfloat16 l = __float2bfloat16(r);
        ((__nv_bfloat16*)(sm + SW2H))[n * KP2 + k] = h;
        ((__nv_bfloat16*)(sm + SW2L))[n * KP2 + k] = l;
    }
    if (tid < MSG_HID) ((float*)(sm + SB1))[tid] = b1[tid];
    if (tid < HID) ((float*)(sm + SB2))[tid] = b2[tid];
    __syncthreads();

    char* A1H = sm + SA + wid * SA_WARP;
    char* A1L = A1H + SA_HALF;
    const int* src = ei;
    const int* dst = ei + N_EDGES;
    const float* b1s = (const float*)(sm + SB1);
    const float* b2s = (const float*)(sm + SB2);

    int g = lane >> 2, tg = lane & 3;

    for (int tile = blockIdx.x * EK_WARPS + wid; tile < N_TILES;
         tile += gridDim.x * EK_WARPS) {
        int e0 = tile * 16;

        // ---- stage 16 edges x 144 ch (hi/lo bf16) into warp A tile ----
        for (int el = 0; el < 16; el++) {
            int e = e0 + el;
            int dv = __ldg(dst + e);
            int sv = __ldg(src + e);
            const float* xd = g_x + dv * HID;
            const float* xs = g_x + sv * HID;
            for (int cp = lane; cp < 72; cp += 32) {
                int ch = cp * 2;
                float2 v;
                if (ch < HID) v = *(const float2*)(xd + ch);
                else if (ch < 2 * HID) v = *(const float2*)(xs + ch - HID);
                else v = *(const float2*)(ea + e * EDGE_DIM + ch - 2 * HID);
                uint32_t hi, lo;
                split2(v.x, v.y, hi, lo);
                *(uint32_t*)(A1H + el * (KP1 * 2) + cp * 4) = hi;
                *(uint32_t*)(A1L + el * (KP1 * 2) + cp * 4) = lo;
            }
        }
        __syncwarp();

        // ---- layer 1: D1[16,128] = split3(A1 x W1), K=144 (9 k-steps) ----
        float c1[16][4];
#pragma unroll
        for (int nt = 0; nt < 16; nt++)
#pragma unroll
            for (int j = 0; j < 4; j++) c1[nt][j] = 0.f;

        for (int ks = 0; ks < 9; ks++) {
            int kb = ks * 32 + tg * 4;   // byte offset of k pair
            uint32_t ah[4], al[4];
            ah[0] = *(uint32_t*)(A1H + g * (KP1 * 2) + kb);
            ah[1] = *(uint32_t*)(A1H + (g + 8) * (KP1 * 2) + kb);
            ah[2] = *(uint32_t*)(A1H + g * (KP1 * 2) + kb + 16);
            ah[3] = *(uint32_t*)(A1H + (g + 8) * (KP1 * 2) + kb + 16);
            al[0] = *(uint32_t*)(A1L + g * (KP1 * 2) + kb);
            al[1] = *(uint32_t*)(A1L + (g + 8) * (KP1 * 2) + kb);
            al[2] = *(uint32_t*)(A1L + g * (KP1 * 2) + kb + 16);
            al[3] = *(uint32_t*)(A1L + (g + 8) * (KP1 * 2) + kb + 16);
#pragma unroll
            for (int nt = 0; nt < 16; nt++) {
                const char* wrh = sm + SW1H + (nt * 8 + g) * (KP1 * 2) + kb;
                const char* wrl = sm + SW1L + (nt * 8 + g) * (KP1 * 2) + kb;
                uint32_t bh0 = *(const uint32_t*)wrh;
                uint32_t bh1 = *(const uint32_t*)(wrh + 16);
                uint32_t bl0 = *(const uint32_t*)wrl;
                uint32_t bl1 = *(const uint32_t*)(wrl + 16);
                mma16816(c1[nt], ah, bh0, bh1);
                mma16816(c1[nt], ah, bl0, bl1);
                mma16816(c1[nt], al, bh0, bh1);
            }
        }

        // ---- epilogue 1: bias+relu, build layer-2 A fragments in regs ----
        uint32_t a2h[8][4], a2l[8][4];
#pragma unroll
        for (int nt = 0; nt < 16; nt++) {
            float2 bb = *(const float2*)(b1s + nt * 8 + tg * 2);
            float h0 = fmaxf(c1[nt][0] + bb.x, 0.f);
            float h1 = fmaxf(c1[nt][1] + bb.y, 0.f);
            float h2 = fmaxf(c1[nt][2] + bb.x, 0.f);
            float h3 = fmaxf(c1[nt][3] + bb.y, 0.f);
            uint32_t hiA, loA, hiB, loB;
            split2(h0, h1, hiA, loA);
            split2(h2, h3, hiB, loB);
            int s = nt >> 1;
            if (nt & 1) {
                a2h[s][2] = hiA; a2h[s][3] = hiB;
                a2l[s][2] = loA; a2l[s][3] = loB;
            } else {
                a2h[s][0] = hiA; a2h[s][1] = hiB;
                a2l[s][0] = loA; a2l[s][1] = loB;
            }
        }

        // ---- layer 2: D2[16,64] = split3(H x W2), K=128 (8 k-steps) ----
        float c2[8][4];
#pragma unroll
        for (int nt = 0; nt < 8; nt++)
#pragma unroll
            for (int j = 0; j < 4; j++) c2[nt][j] = 0.f;

#pragma unroll
        for (int s = 0; s < 8; s++) {
            int kb = s * 32 + tg * 4;
#pragma unroll
            for (int nt = 0; nt < 8; nt++) {
                const char* wrh = sm + SW2H + (nt * 8 + g) * (KP2 * 2) + kb;
                const char* wrl = sm + SW2L + (nt * 8 + g) * (KP2 * 2) + kb;
                uint32_t bh0 = *(const uint32_t*)wrh;
                uint32_t bh1 = *(const uint32_t*)(wrh + 16);
                uint32_t bl0 = *(const uint32_t*)wrl;
                uint32_t bl1 = *(const uint32_t*)(wrl + 16);
                mma16816(c2[nt], a2h[s], bh0, bh1);
                mma16816(c2[nt], a2h[s], bl0, bl1);
                mma16816(c2[nt], a2l[s], bh0, bh1);
            }
        }

        // ---- scatter-add with bias ----
        int d0 = __ldg(dst + e0 + g);
        int d1 = __ldg(dst + e0 + g + 8);
#pragma unroll
        for (int nt = 0; nt < 8; nt++) {
            float2 bb = *(const float2*)(b2s + nt * 8 + tg * 2);
            int col = nt * 8 + tg * 2;
            atomicAdd(&g_m[d0 * HID + col], c2[nt][0] + bb.x);
            atomicAdd(&g_m[d0 * HID + col + 1], c2[nt][1] + bb.y);
            atomicAdd(&g_m[d1 * HID + col], c2[nt][2] + bb.x);
            atomicAdd(&g_m[d1 * HID + col + 1], c2[nt][3] + bb.y);
        }
        __syncwarp();
    }
}

// --------------------------------- GRU -------------------------------------
#define GK_THREADS 256
#define GK_WARPS 8
#define NPW 4
#define GRU_SMEM_F (64 * 96 * 2 * 2 + 384 + GK_WARPS * NPW * 128 * 2)

__global__ __launch_bounds__(GK_THREADS, 1)
void gru_kernel(const float* __restrict__ Wih, const float* __restrict__ Whh,
                const float* __restrict__ bih, const float* __restrict__ bhh) {
    extern __shared__ float s[];
    float2* WihT2 = (float2*)s;                 // [c(64)][p(96)]
    float2* WhhT2 = WihT2 + 64 * 96;
    float* bihs = (float*)(WhhT2 + 64 * 96);    // 192
    float* bhhs = bihs + 192;                   // 192
    float2* stg = (float2*)(bhhs + 192);        // [warp][NPW][128] dup (m|h)

    int tid = threadIdx.x;
    for (int idx = tid; idx < 64 * 96; idx += GK_THREADS) {
        int c = idx / 96, p = idx % 96;
        WihT2[c * 96 + p] = make_float2(Wih[(2 * p) * HID + c],
                                        Wih[(2 * p + 1) * HID + c]);
        WhhT2[c * 96 + p] = make_float2(Whh[(2 * p) * HID + c],
                                        Whh[(2 * p + 1) * HID + c]);
    }
    for (int idx = tid; idx < 192; idx += GK_THREADS) {
        bihs[idx] = bih[idx];
        bhhs[idx] = bhh[idx];
    }
    __syncthreads();

    int warp = tid >> 5, lane = tid & 31;
    float2* ws = stg + warp * NPW * 128;
    const int ngroups = N_NODES / NPW;  // 12500

    for (int g = blockIdx.x * GK_WARPS + warp; g < ngroups;
         g += gridDim.x * GK_WARPS) {
        int v0 = g * NPW;
#pragma unroll
        for (int n = 0; n < NPW; n++) {
            int v = v0 + n;
            float m0 = g_m[v * HID + lane];
            float m1 = g_m[v * HID + lane + 32];
            float h0 = g_x[v * HID + lane];
            float h1 = g_x[v * HID + lane + 32];
            ws[n * 128 + lane] = make_float2(m0, m0);
            ws[n * 128 + lane + 32] = make_float2(m1, m1);
            ws[n * 128 + 64 + lane] = make_float2(h0, h0);
            ws[n * 128 + 64 + lane + 32] = make_float2(h1, h1);
        }
        __syncwarp();

        unsigned long long ai[NPW][3], ah[NPW][3];
#pragma unroll
        for (int n = 0; n < NPW; n++)
#pragma unroll
            for (int j = 0; j < 3; j++) { ai[n][j] = 0ull; ah[n][j] = 0ull; }

#pragma unroll 2
        for (int c = 0; c < HID; c++) {
            unsigned long long wi0 = ld2u((const float*)(WihT2 + c * 96 + lane));
            unsigned long long wi1 = ld2u((const float*)(WihT2 + c * 96 + lane + 32));
            unsigned long long wi2 = ld2u((const float*)(WihT2 + c * 96 + lane + 64));
            unsigned long long wh0 = ld2u((const float*)(WhhT2 + c * 96 + lane));
            unsigned long long wh1 = ld2u((const float*)(WhhT2 + c * 96 + lane + 32));
            unsigned long long wh2 = ld2u((const float*)(WhhT2 + c * 96 + lane + 64));
#pragma unroll
            for (int n = 0; n < NPW; n++) {
                unsigned long long mv = ld2u((const float*)(ws + n * 128 + c));
                unsigned long long hv = ld2u((const float*)(ws + n * 128 + 64 + c));
                ai[n][0] = fma2(wi0, mv, ai[n][0]);
                ai[n][1] = fma2(wi1, mv, ai[n][1]);
                ai[n][2] = fma2(wi2, mv, ai[n][2]);
                ah[n][0] = fma2(wh0, hv, ah[n][0]);
                ah[n][1] = fma2(wh1, hv, ah[n][1]);
                ah[n][2] = fma2(wh2, hv, ah[n][2]);
            }
        }

        int u0 = 2 * lane;
#pragma unroll
        for (int n = 0; n < NPW; n++) {
            int v = v0 + n;
            float2 ir = unpk(ai[n][0]), hr = unpk(ah[n][0]);
            float2 iz = unpk(ai[n][1]), hz = unpk(ah[n][1]);
            float2 in_ = unpk(ai[n][2]), hn = unpk(ah[n][2]);
            float holdA = ws[n * 128 + 64 + u0].x;
            float holdB = ws[n * 128 + 64 + u0 + 1].x;
            float rA = sigmoidf_(ir.x + bihs[u0] + hr.x + bhhs[u0]);
            float rB = sigmoidf_(ir.y + bihs[u0 + 1] + hr.y + bhhs[u0 + 1]);
            float zA = sigmoidf_(iz.x + bihs[64 + u0] + hz.x + bhhs[64 + u0]);
            float zB = sigmoidf_(iz.y + bihs[64 + u0 + 1] + hz.y + bhhs[64 + u0 + 1]);
            float nA = tanhf(in_.x + bihs[128 + u0] + rA * (hn.x + bhhs[128 + u0]));
            float nB = tanhf(in_.y + bihs[128 + u0 + 1] + rB * (hn.y + bhhs[128 + u0 + 1]));
            float oA = (1.f - zA) * nA + zA * holdA;
            float oB = (1.f - zB) * nB + zB * holdB;
            *(float2*)(g_x + v * HID + u0) = make_float2(oA, oB);
        }
        __syncwarp();
    }
}

// ------------------------------- LSTM cell ---------------------------------
#define LSTM_SMEM_F (256 * 128 + 256 * 64 + 4 * 128 + 4 * 64)

__global__ __launch_bounds__(256, 1)
void lstm_kernel(const float* __restrict__ Wih, const float* __restrict__ Whh,
                 const float* __restrict__ bih, const float* __restrict__ bhh) {
    extern __shared__ float s[];
    float* WihT = s;                   // [c(128)][gate(256)]
    float* WhhT = WihT + 256 * 128;    // [c(64)][gate(256)]
    float* qs_s = WhhT + 256 * 64;     // [4][128]
    float* qh_s = qs_s + 4 * 128;      // [4][64]

    int tid = threadIdx.x;
    for (int idx = tid; idx < 256 * 128; idx += 256) {
        int g = idx >> 7, c = idx & 127;
        WihT[c * 256 + g] = Wih[idx];
    }
    for (int idx = tid; idx < 256 * 64; idx += 256) {
        int g = idx >> 6, c = idx & 63;
        WhhT[c * 256 + g] = Whh[idx];
    }
    int g0 = blockIdx.x * 4;
    for (int idx = tid; idx < 4 * 128; idx += 256)
        qs_s[idx] = g_qstar[g0 * 128 + idx];
    for (int idx = tid; idx < 4 * 64; idx += 256)
        qh_s[idx] = g_qh[g0 * 64 + idx];
    __syncthreads();

    int lg = tid >> 6;
    int u = tid & 63;
    int g = g0 + lg;
    float accI = bih[u] + bhh[u];
    float accF = bih[64 + u] + bhh[64 + u];
    float accG = bih[128 + u] + bhh[128 + u];
    float accO = bih[192 + u] + bhh[192 + u];
    const float* qs = qs_s + lg * 128;
#pragma unroll 4
    for (int c = 0; c < 128; c++) {
        float v = qs[c];
        const float* w = &WihT[c * 256];
        accI += v * w[u];
        accF += v * w[64 + u];
        accG += v * w[128 + u];
        accO += v * w[192 + u];
    }
    const float* qh = qh_s + lg * 64;
#pragma unroll 4
    for (int c = 0; c < 64; c++) {
        float v = qh[c];
        const float* w = &WhhT[c * 256];
        accI += v * w[u];
        accF += v * w[64 + u];
        accG += v * w[128 + u];
        accO += v * w[192 + u];
    }
    float i_ = sigmoidf_(accI), f_ = sigmoidf_(accF);
    float gg = tanhf(accG), o_ = sigmoidf_(accO);
    float c_new = f_ * g_qc[g * 64 + u] + i_ * gg;
    float h_new = o_ * tanhf(c_new);
    g_qc[g * 64 + u] = c_new;
    g_qh[g * 64 + u] = h_new;
}

// ----------------------------- attention steps -----------------------------
__global__ void attn_dot_kernel(const int* __restrict__ batch) {
    int wg = (blockIdx.x * blockDim.x + threadIdx.x) >> 5;
    int lane = threadIdx.x & 31;
    if (wg >= N_NODES) return;
    int v = wg;
    int b = batch[v];
    float p = g_x[v * HID + lane] * g_qh[b * HID + lane] +
              g_x[v * HID + lane + 32] * g_qh[b * HID + lane + 32];
#pragma unroll
    for (int o = 16; o; o >>= 1) p += __shfl_down_sync(0xffffffffu, p, o);
    if (lane == 0) {
        g_e[v] = p;
        atomicMax(&g_emax[b], enc_f(p));
    }
}

__global__ void attn_exp_kernel(const int* __restrict__ batch) {
    int v = blockIdx.x * blockDim.x + threadIdx.x;
    if (v >= N_NODES) return;
    int b = batch[v];
    float a = expf(g_e[v] - dec_f(g_emax[b]));
    g_a[v] = a;
    atomicAdd(&g_asum[b], a);
}

__global__ void attn_rvec_kernel(const int* __restrict__ batch) {
    int wg = (blockIdx.x * blockDim.x + threadIdx.x) >> 5;
    int lane = threadIdx.x & 31;
    if (wg >= N_NODES) return;
    int v = wg;
    int b = batch[v];
    float coef = g_a[v] / g_asum[b];
    atomicAdd(&g_rvec[b * HID + lane], coef * g_x[v * HID + lane]);
    atomicAdd(&g_rvec[b * HID + lane + 32], coef * g_x[v * HID + lane + 32]);
}

__global__ void qstar_kernel() {
    int t = blockIdx.x * blockDim.x + threadIdx.x;
    if (t >= NUM_GRAPHS * HID) return;
    int g = t >> 6, u = t & 63;
    g_qstar[g * 2 * HID + u] = g_qh[t];
    g_qstar[g * 2 * HID + HID + u] = g_rvec[t];
}

// ------------------------------- regressor ---------------------------------
__global__ void reg_kernel(const float* __restrict__ W1,
                           const float* __restrict__ b1,
                           const float* __restrict__ W2,
                           const float* __restrict__ b2,
                           float* __restrict__ out) {
    __shared__ float qs[128];
    __shared__ float red[64];
    int g = blockIdx.x;
    int u = threadIdx.x;  // 64 threads
    qs[u] = g_qstar[g * 128 + u];
    qs[u + 64] = g_qstar[g * 128 + u + 64];
    __syncthreads();
    float acc = b1[u];
#pragma unroll 4
    for (int c = 0; c < 128; c++) acc += qs[c] * W1[c * HID + u];
    red[u] = fmaxf(acc, 0.f) * W2[u];
    __syncthreads();
    for (int sft = 32; sft; sft >>= 1) {
        if (u < sft) red[u] += red[u + sft];
        __syncthreads();
    }
    if (u == 0) out[g] = red[0] + b2[0];
}

// ------------------------------ host driver --------------------------------
extern "C" void kernel_launch(void* const* d_in, const int* in_sizes, int n_in,
                              void* d_out, int out_size) {
    const float* x_feat     = (const float*)d_in[0];
    const int*   edge_index = (const int*)d_in[1];
    const float* edge_attr  = (const float*)d_in[2];
    const int*   batch      = (const int*)d_in[3];
    const float* W_emb = (const float*)d_in[4];
    const float* b_emb = (const float*)d_in[5];
    const float* W_m1  = (const float*)d_in[6];
    const float* b_m1  = (const float*)d_in[7];
    const float* W_m2  = (const float*)d_in[8];
    const float* b_m2  = (const float*)d_in[9];
    const float* gWih  = (const float*)d_in[10];
    const float* gWhh  = (const float*)d_in[11];
    const float* gbih  = (const float*)d_in[12];
    const float* gbhh  = (const float*)d_in[13];
    const float* lWih  = (const float*)d_in[14];
    const float* lWhh  = (const float*)d_in[15];
    const float* lbih  = (const float*)d_in[16];
    const float* lbhh  = (const float*)d_in[17];
    const float* Wr1   = (const float*)d_in[18];
    const float* br1   = (const float*)d_in[19];
    const float* Wr2   = (const float*)d_in[20];
    const float* br2   = (const float*)d_in[21];
    float* out = (float*)d_out;

    const int gru_smem  = GRU_SMEM_F * (int)sizeof(float);
    const int lstm_smem = LSTM_SMEM_F * (int)sizeof(float);
    cudaFuncSetAttribute(edge_msg_kernel,
                         cudaFuncAttributeMaxDynamicSharedMemorySize, EK_SMEM_BYTES);
    cudaFuncSetAttribute(gru_kernel,
                         cudaFuncAttributeMaxDynamicSharedMemorySize, gru_smem);
    cudaFuncSetAttribute(lstm_kernel,
                         cudaFuncAttributeMaxDynamicSharedMemorySize, lstm_smem);

    // 1. node embedding
    embed_kernel<<<(N_NODES * HID + 255) / 256, 256>>>(x_feat, W_emb, b_emb);

    // 2. message passing rounds
    for (int r = 0; r < NUM_MP; r++) {
        zero_m_kernel<<<(N_NODES * HID + 255) / 256, 256>>>();
        edge_msg_kernel<<<148, 256, EK_SMEM_BYTES>>>(edge_index, edge_attr,
                                                     W_m1, b_m1, W_m2, b_m2);
        gru_kernel<<<148, GK_THREADS, gru_smem>>>(gWih, gWhh, gbih, gbhh);
    }

    // 3. Set2Set
    zero_s2s_state_kernel<<<(NUM_GRAPHS * 2 * HID + 255) / 256, 256>>>();
    for (int s = 0; s < S2S_STEPS; s++) {
        lstm_kernel<<<NUM_GRAPHS / 4, 256, lstm_smem>>>(lWih, lWhh, lbih, lbhh);
        zero_attn_kernel<<<(NUM_GRAPHS * HID + 255) / 256, 256>>>();
        attn_dot_kernel<<<(N_NODES * 32 + 255) / 256, 256>>>(batch);
        attn_exp_kernel<<<(N_NODES + 255) / 256, 256>>>(batch);
        attn_rvec_kernel<<<(N_NODES * 32 + 255) / 256, 256>>>(batch);
        qstar_kernel<<<(NUM_GRAPHS * HID + 255) / 256, 256>>>();
    }

    // 4. regressor
    reg_kernel<<<NUM_GRAPHS, 64>>>(Wr1, br1, Wr2, br2, out);
    (void)in_sizes; (void)n_in; (void)out_size;
}

// round 15
// speedup vs baseline: 1.5743x; 1.2266x over previous
#include <cuda_runtime.h>
#include <cuda_bf16.h>
#include <cstdint>

// ---------------------------------------------------------------------------
// MPNN forward, graph-capturable, allocation-free.
// R15: R14 mma.sync edge MLP with 12 warps/CTA + fully fused per-graph
// Set2Set attention kernel (1 block/graph, no global atomics, 2 launches/step).
// ---------------------------------------------------------------------------

#define N_NODES 50000
#define N_EDGES 800000
#define NODE_DIM 32
#define EDGE_DIM 16
#define HID 64
#define MSG_HID 128
#define NUM_GRAPHS 512
#define NUM_MP 3
#define S2S_STEPS 6
#define IN_DIM (2 * HID + EDGE_DIM)  // 144

// ------------------------- scratch (device globals) ------------------------
__device__ __align__(16) float g_x[N_NODES * HID];
__device__ __align__(16) float g_m[N_NODES * HID];
__device__ float g_qh[NUM_GRAPHS * HID];
__device__ float g_qc[NUM_GRAPHS * HID];
__device__ float g_qstar[NUM_GRAPHS * 2 * HID];
__device__ float g_e[N_NODES];

__device__ __forceinline__ float sigmoidf_(float x) { return 1.f / (1.f + expf(-x)); }

// ----------------------- packed f32x2 helpers (GRU) ------------------------
__device__ __forceinline__ unsigned long long fma2(unsigned long long a,
                                                   unsigned long long b,
                                                   unsigned long long c) {
    unsigned long long d;
    asm("fma.rn.f32x2 %0, %1, %2, %3;" : "=l"(d) : "l"(a), "l"(b), "l"(c));
    return d;
}
__device__ __forceinline__ float2 unpk(unsigned long long v) {
    float lo, hi;
    asm("mov.b64 {%0, %1}, %2;" : "=f"(lo), "=f"(hi) : "l"(v));
    return make_float2(lo, hi);
}
__device__ __forceinline__ unsigned long long ld2u(const float* p) {
    return *(const unsigned long long*)p;
}

// --------------------------- mma.sync primitives ---------------------------
__device__ __forceinline__ void split2(float a, float b, uint32_t& hi, uint32_t& lo) {
    uint32_t h;
    asm("cvt.rn.bf16x2.f32 %0, %1, %2;" : "=r"(h) : "f"(b), "f"(a));  // low=a
    float ra = a - __uint_as_float(h << 16);
    float rb = b - __uint_as_float(h & 0xffff0000u);
    uint32_t l;
    asm("cvt.rn.bf16x2.f32 %0, %1, %2;" : "=r"(l) : "f"(rb), "f"(ra));
    hi = h; lo = l;
}

__device__ __forceinline__ void mma16816(float* c, const uint32_t* a,
                                         uint32_t b0, uint32_t b1) {
    asm volatile(
        "mma.sync.aligned.m16n8k16.row.col.f32.bf16.bf16.f32 "
        "{%0,%1,%2,%3}, {%4,%5,%6,%7}, {%8,%9}, {%0,%1,%2,%3};"
        : "+f"(c[0]), "+f"(c[1]), "+f"(c[2]), "+f"(c[3])
        : "r"(a[0]), "r"(a[1]), "r"(a[2]), "r"(a[3]), "r"(b0), "r"(b1));
}

// ------------------------------ zero kernels -------------------------------
__global__ void zero_m_kernel() {
    int t = blockIdx.x * blockDim.x + threadIdx.x;
    if (t < N_NODES * HID) g_m[t] = 0.f;
}
__global__ void zero_s2s_state_kernel() {
    int t = blockIdx.x * blockDim.x + threadIdx.x;
    if (t < NUM_GRAPHS * HID) { g_qh[t] = 0.f; g_qc[t] = 0.f; }
    if (t < NUM_GRAPHS * 2 * HID) g_qstar[t] = 0.f;
}

// ------------------------------- embedding ---------------------------------
__global__ void embed_kernel(const float* __restrict__ xf,
                             const float* __restrict__ W,
                             const float* __restrict__ b) {
    int t = blockIdx.x * blockDim.x + threadIdx.x;
    if (t >= N_NODES * HID) return;
    int v = t >> 6, o = t & 63;
    const float* xr = xf + v * NODE_DIM;
    float acc = b[o];
#pragma unroll
    for (int c = 0; c < NODE_DIM; c++) acc += xr[c] * W[c * HID + o];
    g_x[t] = acc;
}

// ---------------------- edge message MLP on mma.sync -----------------------
#define KP1 152
#define KP2 136
#define SW1H 0                          // [128][KP1] bf16
#define SW1L (SW1H + 128 * KP1 * 2)
#define SW2H (SW1L + 128 * KP1 * 2)     // [64][KP2] bf16
#define SW2L (SW2H + 64 * KP2 * 2)
#define SB1  (SW2L + 64 * KP2 * 2)      // 128 f32
#define SB2  (SB1 + 512)                // 64 f32
#define SA   (SB2 + 256)
#define SA_HALF (16 * KP1 * 2)          // 4864B
#define SA_WARP (2 * SA_HALF)           // 9728B
#define EK_WARPS 12
#define EK_THREADS (EK_WARPS * 32)
#define EK_SMEM_BYTES (SA + EK_WARPS * SA_WARP)   // 230144B

#define N_TILES (N_EDGES / 16)  // 50000

__global__ __launch_bounds__(EK_THREADS, 1)
void edge_msg_kernel(const int* __restrict__ ei, const float* __restrict__ ea,
                     const float* __restrict__ W1, const float* __restrict__ b1,
                     const float* __restrict__ W2, const float* __restrict__ b2) {
    extern __shared__ char sm[];
    int tid = threadIdx.x;
    int lane = tid & 31, wid = tid >> 5;

    for (int idx = tid; idx < IN_DIM * MSG_HID; idx += EK_THREADS) {
        int k = idx >> 7, n = idx & 127;
        float w = W1[idx];
        __nv_bfloat16 h = __float2bfloat16(w);
        float r = w - __bfloat162float(h);
        __nv_bfloat16 l = __float2bfloat16(r);
        ((__nv_bfloat16*)(sm + SW1H))[n * KP1 + k] = h;
        ((__nv_bfloat16*)(sm + SW1L))[n * KP1 + k] = l;
    }
    for (int idx = tid; idx < MSG_HID * HID; idx += EK_THREADS) {
        int k = idx >> 6, n = idx & 63;
        float w = W2[idx];
        __nv_bfloat16 h = __float2bfloat16(w);
        float r = w - __bfloat162float(h);
        __nv_bfloat16 l = __float2bfloat16(r);
        ((__nv_bfloat16*)(sm + SW2H))[n * KP2 + k] = h;
        ((__nv_bfloat16*)(sm + SW2L))[n * KP2 + k] = l;
    }
    if (tid < MSG_HID) ((float*)(sm + SB1))[tid] = b1[tid];
    if (tid < HID) ((float*)(sm + SB2))[tid] = b2[tid];
    __syncthreads();

    char* A1H = sm + SA + wid * SA_WARP;
    char* A1L = A1H + SA_HALF;
    const int* src = ei;
    const int* dst = ei + N_EDGES;
    const float* b1s = (const float*)(sm + SB1);
    const float* b2s = (const float*)(sm + SB2);

    int g = lane >> 2, tg = lane & 3;

    for (int tile = blockIdx.x * EK_WARPS + wid; tile < N_TILES;
         tile += gridDim.x * EK_WARPS) {
        int e0 = tile * 16;

        // ---- stage 16 edges x 144 ch (hi/lo bf16) ----
        for (int el = 0; el < 16; el++) {
            int e = e0 + el;
            int dv = __ldg(dst + e);
            int sv = __ldg(src + e);
            const float* xd = g_x + dv * HID;
            const float* xs = g_x + sv * HID;
            for (int cp = lane; cp < 72; cp += 32) {
                int ch = cp * 2;
                float2 v;
                if (ch < HID) v = *(const float2*)(xd + ch);
                else if (ch < 2 * HID) v = *(const float2*)(xs + ch - HID);
                else v = *(const float2*)(ea + e * EDGE_DIM + ch - 2 * HID);
                uint32_t hi, lo;
                split2(v.x, v.y, hi, lo);
                *(uint32_t*)(A1H + el * (KP1 * 2) + cp * 4) = hi;
                *(uint32_t*)(A1L + el * (KP1 * 2) + cp * 4) = lo;
            }
        }
        __syncwarp();

        // ---- layer 1 ----
        float c1[16][4];
#pragma unroll
        for (int nt = 0; nt < 16; nt++)
#pragma unroll
            for (int j = 0; j < 4; j++) c1[nt][j] = 0.f;

        for (int ks = 0; ks < 9; ks++) {
            int kb = ks * 32 + tg * 4;
            uint32_t ah[4], al[4];
            ah[0] = *(uint32_t*)(A1H + g * (KP1 * 2) + kb);
            ah[1] = *(uint32_t*)(A1H + (g + 8) * (KP1 * 2) + kb);
            ah[2] = *(uint32_t*)(A1H + g * (KP1 * 2) + kb + 16);
            ah[3] = *(uint32_t*)(A1H + (g + 8) * (KP1 * 2) + kb + 16);
            al[0] = *(uint32_t*)(A1L + g * (KP1 * 2) + kb);
            al[1] = *(uint32_t*)(A1L + (g + 8) * (KP1 * 2) + kb);
            al[2] = *(uint32_t*)(A1L + g * (KP1 * 2) + kb + 16);
            al[3] = *(uint32_t*)(A1L + (g + 8) * (KP1 * 2) + kb + 16);
#pragma unroll
            for (int nt = 0; nt < 16; nt++) {
                const char* wrh = sm + SW1H + (nt * 8 + g) * (KP1 * 2) + kb;
                const char* wrl = sm + SW1L + (nt * 8 + g) * (KP1 * 2) + kb;
                uint32_t bh0 = *(const uint32_t*)wrh;
                uint32_t bh1 = *(const uint32_t*)(wrh + 16);
                uint32_t bl0 = *(const uint32_t*)wrl;
                uint32_t bl1 = *(const uint32_t*)(wrl + 16);
                mma16816(c1[nt], ah, bh0, bh1);
                mma16816(c1[nt], ah, bl0, bl1);
                mma16816(c1[nt], al, bh0, bh1);
            }
        }

        // ---- epilogue 1: bias+relu -> layer-2 A fragments (registers) ----
        uint32_t a2h[8][4], a2l[8][4];
#pragma unroll
        for (int nt = 0; nt < 16; nt++) {
            float2 bb = *(const float2*)(b1s + nt * 8 + tg * 2);
            float h0 = fmaxf(c1[nt][0] + bb.x, 0.f);
            float h1 = fmaxf(c1[nt][1] + bb.y, 0.f);
            float h2 = fmaxf(c1[nt][2] + bb.x, 0.f);
            float h3 = fmaxf(c1[nt][3] + bb.y, 0.f);
            uint32_t hiA, loA, hiB, loB;
            split2(h0, h1, hiA, loA);
            split2(h2, h3, hiB, loB);
            int s = nt >> 1;
            if (nt & 1) {
                a2h[s][2] = hiA; a2h[s][3] = hiB;
                a2l[s][2] = loA; a2l[s][3] = loB;
            } else {
                a2h[s][0] = hiA; a2h[s][1] = hiB;
                a2l[s][0] = loA; a2l[s][1] = loB;
            }
        }

        // ---- layer 2 ----
        float c2[8][4];
#pragma unroll
        for (int nt = 0; nt < 8; nt++)
#pragma unroll
            for (int j = 0; j < 4; j++) c2[nt][j] = 0.f;

#pragma unroll
        for (int s = 0; s < 8; s++) {
            int kb = s * 32 + tg * 4;
#pragma unroll
            for (int nt = 0; nt < 8; nt++) {
                const char* wrh = sm + SW2H + (nt * 8 + g) * (KP2 * 2) + kb;
                const char* wrl = sm + SW2L + (nt * 8 + g) * (KP2 * 2) + kb;
                uint32_t bh0 = *(const uint32_t*)wrh;
                uint32_t bh1 = *(const uint32_t*)(wrh + 16);
                uint32_t bl0 = *(const uint32_t*)wrl;
                uint32_t bl1 = *(const uint32_t*)(wrl + 16);
                mma16816(c2[nt], a2h[s], bh0, bh1);
                mma16816(c2[nt], a2h[s], bl0, bl1);
                mma16816(c2[nt], a2l[s], bh0, bh1);
            }
        }

        // ---- scatter-add with bias ----
        int d0 = __ldg(dst + e0 + g);
        int d1 = __ldg(dst + e0 + g + 8);
#pragma unroll
        for (int nt = 0; nt < 8; nt++) {
            float2 bb = *(const float2*)(b2s + nt * 8 + tg * 2);
            int col = nt * 8 + tg * 2;
            atomicAdd(&g_m[d0 * HID + col], c2[nt][0] + bb.x);
            atomicAdd(&g_m[d0 * HID + col + 1], c2[nt][1] + bb.y);
            atomicAdd(&g_m[d1 * HID + col], c2[nt][2] + bb.x);
            atomicAdd(&g_m[d1 * HID + col + 1], c2[nt][3] + bb.y);
        }
        __syncwarp();
    }
}

// --------------------------------- GRU -------------------------------------
#define GK_THREADS 256
#define GK_WARPS 8
#define NPW 4
#define GRU_SMEM_F (64 * 96 * 2 * 2 + 384 + GK_WARPS * NPW * 128 * 2)

__global__ __launch_bounds__(GK_THREADS, 1)
void gru_kernel(const float* __restrict__ Wih, const float* __restrict__ Whh,
                const float* __restrict__ bih, const float* __restrict__ bhh) {
    extern __shared__ float s[];
    float2* WihT2 = (float2*)s;                 // [c(64)][p(96)]
    float2* WhhT2 = WihT2 + 64 * 96;
    float* bihs = (float*)(WhhT2 + 64 * 96);    // 192
    float* bhhs = bihs + 192;                   // 192
    float2* stg = (float2*)(bhhs + 192);        // [warp][NPW][128] dup (m|h)

    int tid = threadIdx.x;
    for (int idx = tid; idx < 64 * 96; idx += GK_THREADS) {
        int c = idx / 96, p = idx % 96;
        WihT2[c * 96 + p] = make_float2(Wih[(2 * p) * HID + c],
                                        Wih[(2 * p + 1) * HID + c]);
        WhhT2[c * 96 + p] = make_float2(Whh[(2 * p) * HID + c],
                                        Whh[(2 * p + 1) * HID + c]);
    }
    for (int idx = tid; idx < 192; idx += GK_THREADS) {
        bihs[idx] = bih[idx];
        bhhs[idx] = bhh[idx];
    }
    __syncthreads();

    int warp = tid >> 5, lane = tid & 31;
    float2* ws = stg + warp * NPW * 128;
    const int ngroups = N_NODES / NPW;  // 12500

    for (int g = blockIdx.x * GK_WARPS + warp; g < ngroups;
         g += gridDim.x * GK_WARPS) {
        int v0 = g * NPW;
#pragma unroll
        for (int n = 0; n < NPW; n++) {
            int v = v0 + n;
            float m0 = g_m[v * HID + lane];
            float m1 = g_m[v * HID + lane + 32];
            float h0 = g_x[v * HID + lane];
            float h1 = g_x[v * HID + lane + 32];
            ws[n * 128 + lane] = make_float2(m0, m0);
            ws[n * 128 + lane + 32] = make_float2(m1, m1);
            ws[n * 128 + 64 + lane] = make_float2(h0, h0);
            ws[n * 128 + 64 + lane + 32] = make_float2(h1, h1);
        }
        __syncwarp();

        unsigned long long ai[NPW][3], ah[NPW][3];
#pragma unroll
        for (int n = 0; n < NPW; n++)
#pragma unroll
            for (int j = 0; j < 3; j++) { ai[n][j] = 0ull; ah[n][j] = 0ull; }

#pragma unroll 2
        for (int c = 0; c < HID; c++) {
            unsigned long long wi0 = ld2u((const float*)(WihT2 + c * 96 + lane));
            unsigned long long wi1 = ld2u((const float*)(WihT2 + c * 96 + lane + 32));
            unsigned long long wi2 = ld2u((const float*)(WihT2 + c * 96 + lane + 64));
            unsigned long long wh0 = ld2u((const float*)(WhhT2 + c * 96 + lane));
            unsigned long long wh1 = ld2u((const float*)(WhhT2 + c * 96 + lane + 32));
            unsigned long long wh2 = ld2u((const float*)(WhhT2 + c * 96 + lane + 64));
#pragma unroll
            for (int n = 0; n < NPW; n++) {
                unsigned long long mv = ld2u((const float*)(ws + n * 128 + c));
                unsigned long long hv = ld2u((const float*)(ws + n * 128 + 64 + c));
                ai[n][0] = fma2(wi0, mv, ai[n][0]);
                ai[n][1] = fma2(wi1, mv, ai[n][1]);
                ai[n][2] = fma2(wi2, mv, ai[n][2]);
                ah[n][0] = fma2(wh0, hv, ah[n][0]);
                ah[n][1] = fma2(wh1, hv, ah[n][1]);
                ah[n][2] = fma2(wh2, hv, ah[n][2]);
            }
        }

        int u0 = 2 * lane;
#pragma unroll
        for (int n = 0; n < NPW; n++) {
            int v = v0 + n;
            float2 ir = unpk(ai[n][0]), hr = unpk(ah[n][0]);
            float2 iz = unpk(ai[n][1]), hz = unpk(ah[n][1]);
            float2 in_ = unpk(ai[n][2]), hn = unpk(ah[n][2]);
            float holdA = ws[n * 128 + 64 + u0].x;
            float holdB = ws[n * 128 + 64 + u0 + 1].x;
            float rA = sigmoidf_(ir.x + bihs[u0] + hr.x + bhhs[u0]);
            float rB = sigmoidf_(ir.y + bihs[u0 + 1] + hr.y + bhhs[u0 + 1]);
            float zA = sigmoidf_(iz.x + bihs[64 + u0] + hz.x + bhhs[64 + u0]);
            float zB = sigmoidf_(iz.y + bihs[64 + u0 + 1] + hz.y + bhhs[64 + u0 + 1]);
            float nA = tanhf(in_.x + bihs[128 + u0] + rA * (hn.x + bhhs[128 + u0]));
            float nB = tanhf(in_.y + bihs[128 + u0 + 1] + rB * (hn.y + bhhs[128 + u0 + 1]));
            float oA = (1.f - zA) * nA + zA * holdA;
            float oB = (1.f - zB) * nB + zB * holdB;
            *(float2*)(g_x + v * HID + u0) = make_float2(oA, oB);
        }
        __syncwarp();
    }
}

// ------------------------------- LSTM cell ---------------------------------
#define LSTM_SMEM_F (256 * 128 + 256 * 64 + 4 * 128 + 4 * 64)

__global__ __launch_bounds__(256, 1)
void lstm_kernel(const float* __restrict__ Wih, const float* __restrict__ Whh,
                 const float* __restrict__ bih, const float* __restrict__ bhh) {
    extern __shared__ float s[];
    float* WihT = s;                   // [c(128)][gate(256)]
    float* WhhT = WihT + 256 * 128;    // [c(64)][gate(256)]
    float* qs_s = WhhT + 256 * 64;     // [4][128]
    float* qh_s = qs_s + 4 * 128;      // [4][64]

    int tid = threadIdx.x;
    for (int idx = tid; idx < 256 * 128; idx += 256) {
        int g = idx >> 7, c = idx & 127;
        WihT[c * 256 + g] = Wih[idx];
    }
    for (int idx = tid; idx < 256 * 64; idx += 256) {
        int g = idx >> 6, c = idx & 63;
        WhhT[c * 256 + g] = Whh[idx];
    }
    int g0 = blockIdx.x * 4;
    for (int idx = tid; idx < 4 * 128; idx += 256)
        qs_s[idx] = g_qstar[g0 * 128 + idx];
    for (int idx = tid; idx < 4 * 64; idx += 256)
        qh_s[idx] = g_qh[g0 * 64 + idx];
    __syncthreads();

    int lg = tid >> 6;
    int u = tid & 63;
    int g = g0 + lg;
    float accI = bih[u] + bhh[u];
    float accF = bih[64 + u] + bhh[64 + u];
    float accG = bih[128 + u] + bhh[128 + u];
    float accO = bih[192 + u] + bhh[192 + u];
    const float* qs = qs_s + lg * 128;
#pragma unroll 4
    for (int c = 0; c < 128; c++) {
        float v = qs[c];
        const float* w = &WihT[c * 256];
        accI += v * w[u];
        accF += v * w[64 + u];
        accG += v * w[128 + u];
        accO += v * w[192 + u];
    }
    const float* qh = qh_s + lg * 64;
#pragma unroll 4
    for (int c = 0; c < 64; c++) {
        float v = qh[c];
        const float* w = &WhhT[c * 256];
        accI += v * w[u];
        accF += v * w[64 + u];
        accG += v * w[128 + u];
        accO += v * w[192 + u];
    }
    float i_ = sigmoidf_(accI), f_ = sigmoidf_(accF);
    float gg = tanhf(accG), o_ = sigmoidf_(accO);
    float c_new = f_ * g_qc[g * 64 + u] + i_ * gg;
    float h_new = o_ * tanhf(c_new);
    g_qc[g * 64 + u] = c_new;
    g_qh[g * 64 + u] = h_new;
}

// ---------------- fused per-graph Set2Set attention step -------------------
// One block (256 thr) per graph: dot -> max -> exp -> sum -> rvec -> q_star.
__device__ __forceinline__ int lower_bound_i(const int* b, int n, int key) {
    int lo = 0, hi = n;
    while (lo < hi) {
        int m = (lo + hi) >> 1;
        if (__ldg(b + m) < key) lo = m + 1; else hi = m;
    }
    return lo;
}

__global__ __launch_bounds__(256, 4)
void attn_s2s_kernel(const int* __restrict__ batch) {
    __shared__ float qh_s[HID];
    __shared__ float rv[HID];
    __shared__ float red[8];
    __shared__ float emax_s, asum_s;
    __shared__ int s0_s, s1_s;

    int g = blockIdx.x;
    int tid = threadIdx.x;
    int warp = tid >> 5, lane = tid & 31;

    if (tid == 0) {
        s0_s = lower_bound_i(batch, N_NODES, g);
        s1_s = lower_bound_i(batch, N_NODES, g + 1);
        asum_s = 0.f;
    }
    if (tid < HID) { qh_s[tid] = g_qh[g * HID + tid]; rv[tid] = 0.f; }
    __syncthreads();
    int s0 = s0_s, s1 = s1_s;

    // pass 1: e_v = x[v].qh ; block max
    float wmax = -3.4e38f;
    for (int v = s0 + warp; v < s1; v += 8) {
        float p = g_x[v * HID + lane] * qh_s[lane] +
                  g_x[v * HID + lane + 32] * qh_s[lane + 32];
#pragma unroll
        for (int o = 16; o; o >>= 1) p += __shfl_down_sync(0xffffffffu, p, o);
        p = __shfl_sync(0xffffffffu, p, 0);
        if (lane == 0) g_e[v] = p;
        wmax = fmaxf(wmax, p);
    }
    if (lane == 0) red[warp] = wmax;
    __syncthreads();
    if (tid == 0) {
        float m = red[0];
#pragma unroll
        for (int w = 1; w < 8; w++) m = fmaxf(m, red[w]);
        emax_s = m;
    }
    __syncthreads();
    float emax = emax_s;

    // pass 2: a_v = exp(e-emax); asum; rvec (unnormalized)
    float asl = 0.f, r0 = 0.f, r1 = 0.f;
    for (int v = s0 + warp; v < s1; v += 8) {
        float a = expf(g_e[v] - emax);
        asl += a;
        r0 += a * g_x[v * HID + lane];
        r1 += a * g_x[v * HID + lane + 32];
    }
    if (lane == 0 && asl != 0.f) atomicAdd(&asum_s, asl);
    atomicAdd(&rv[lane], r0);
    atomicAdd(&rv[lane + 32], r1);
    __syncthreads();

    // q_star = [qh, rvec/asum]
    if (tid < HID) {
        float denom = asum_s;
        float rval = (s1 > s0) ? rv[tid] / denom : 0.f;
        g_qstar[g * 2 * HID + tid] = qh_s[tid];
        g_qstar[g * 2 * HID + HID + tid] = rval;
    }
}

// ------------------------------- regressor ---------------------------------
__global__ void reg_kernel(const float* __restrict__ W1,
                           const float* __restrict__ b1,
                           const float* __restrict__ W2,
                           const float* __restrict__ b2,
                           float* __restrict__ out) {
    __shared__ float qs[128];
    __shared__ float red[64];
    int g = blockIdx.x;
    int u = threadIdx.x;  // 64 threads
    qs[u] = g_qstar[g * 128 + u];
    qs[u + 64] = g_qstar[g * 128 + u + 64];
    __syncthreads();
    float acc = b1[u];
#pragma unroll 4
    for (int c = 0; c < 128; c++) acc += qs[c] * W1[c * HID + u];
    red[u] = fmaxf(acc, 0.f) * W2[u];
    __syncthreads();
    for (int sft = 32; sft; sft >>= 1) {
        if (u < sft) red[u] += red[u + sft];
        __syncthreads();
    }
    if (u == 0) out[g] = red[0] + b2[0];
}

// ------------------------------ host driver --------------------------------
extern "C" void kernel_launch(void* const* d_in, const int* in_sizes, int n_in,
                              void* d_out, int out_size) {
    const float* x_feat     = (const float*)d_in[0];
    const int*   edge_index = (const int*)d_in[1];
    const float* edge_attr  = (const float*)d_in[2];
    const int*   batch      = (const int*)d_in[3];
    const float* W_emb = (const float*)d_in[4];
    const float* b_emb = (const float*)d_in[5];
    const float* W_m1  = (const float*)d_in[6];
    const float* b_m1  = (const float*)d_in[7];
    const float* W_m2  = (const float*)d_in[8];
    const float* b_m2  = (const float*)d_in[9];
    const float* gWih  = (const float*)d_in[10];
    const float* gWhh  = (const float*)d_in[11];
    const float* gbih  = (const float*)d_in[12];
    const float* gbhh  = (const float*)d_in[13];
    const float* lWih  = (const float*)d_in[14];
    const float* lWhh  = (const float*)d_in[15];
    const float* lbih  = (const float*)d_in[16];
    const float* lbhh  = (const float*)d_in[17];
    const float* Wr1   = (const float*)d_in[18];
    const float* br1   = (const float*)d_in[19];
    const float* Wr2   = (const float*)d_in[20];
    const float* br2   = (const float*)d_in[21];
    float* out = (float*)d_out;

    const int gru_smem  = GRU_SMEM_F * (int)sizeof(float);
    const int lstm_smem = LSTM_SMEM_F * (int)sizeof(float);
    cudaFuncSetAttribute(edge_msg_kernel,
                         cudaFuncAttributeMaxDynamicSharedMemorySize, EK_SMEM_BYTES);
    cudaFuncSetAttribute(gru_kernel,
                         cudaFuncAttributeMaxDynamicSharedMemorySize, gru_smem);
    cudaFuncSetAttribute(lstm_kernel,
                         cudaFuncAttributeMaxDynamicSharedMemorySize, lstm_smem);

    // 1. node embedding
    embed_kernel<<<(N_NODES * HID + 255) / 256, 256>>>(x_feat, W_emb, b_emb);

    // 2. message passing rounds
    for (int r = 0; r < NUM_MP; r++) {
        zero_m_kernel<<<(N_NODES * HID + 255) / 256, 256>>>();
        edge_msg_kernel<<<148, EK_THREADS, EK_SMEM_BYTES>>>(edge_index, edge_attr,
                                                            W_m1, b_m1, W_m2, b_m2);
        gru_kernel<<<148, GK_THREADS, gru_smem>>>(gWih, gWhh, gbih, gbhh);
    }

    // 3. Set2Set — 2 launches per step
    zero_s2s_state_kernel<<<(NUM_GRAPHS * 2 * HID + 255) / 256, 256>>>();
    for (int s = 0; s < S2S_STEPS; s++) {
        lstm_kernel<<<NUM_GRAPHS / 4, 256, lstm_smem>>>(lWih, lWhh, lbih, lbhh);
        attn_s2s_kernel<<<NUM_GRAPHS, 256>>>(batch);
    }

    // 4. regressor
    reg_kernel<<<NUM_GRAPHS, 64>>>(Wr1, br1, Wr2, br2, out);
    (void)in_sizes; (void)n_in; (void)out_size;
}

// round 16
// speedup vs baseline: 2.5116x; 1.5954x over previous
#include <cuda_runtime.h>
#include <cuda_bf16.h>
#include <cstdint>

// ---------------------------------------------------------------------------
// MPNN forward, graph-capturable, allocation-free.
// R16: edge MLP mma.sync with DIRECT global->register A-fragment gather
// (no smem staging, no syncwarp); GRU at 16 warps + fused g_m zeroing;
// fused per-graph Set2Set attention.
// ---------------------------------------------------------------------------

#define N_NODES 50000
#define N_EDGES 800000
#define NODE_DIM 32
#define EDGE_DIM 16
#define HID 64
#define MSG_HID 128
#define NUM_GRAPHS 512
#define NUM_MP 3
#define S2S_STEPS 6
#define IN_DIM (2 * HID + EDGE_DIM)  // 144

// ------------------------- scratch (device globals) ------------------------
__device__ __align__(16) float g_x[N_NODES * HID];
__device__ __align__(16) float g_m[N_NODES * HID];
__device__ float g_qh[NUM_GRAPHS * HID];
__device__ float g_qc[NUM_GRAPHS * HID];
__device__ float g_qstar[NUM_GRAPHS * 2 * HID];
__device__ float g_e[N_NODES];

__device__ __forceinline__ float sigmoidf_(float x) { return 1.f / (1.f + expf(-x)); }

// ----------------------- packed f32x2 helpers (GRU) ------------------------
__device__ __forceinline__ unsigned long long fma2(unsigned long long a,
                                                   unsigned long long b,
                                                   unsigned long long c) {
    unsigned long long d;
    asm("fma.rn.f32x2 %0, %1, %2, %3;" : "=l"(d) : "l"(a), "l"(b), "l"(c));
    return d;
}
__device__ __forceinline__ float2 unpk(unsigned long long v) {
    float lo, hi;
    asm("mov.b64 {%0, %1}, %2;" : "=f"(lo), "=f"(hi) : "l"(v));
    return make_float2(lo, hi);
}
__device__ __forceinline__ unsigned long long ld2u(const float* p) {
    return *(const unsigned long long*)p;
}

// --------------------------- mma.sync primitives ---------------------------
__device__ __forceinline__ void split2(float a, float b, uint32_t& hi, uint32_t& lo) {
    uint32_t h;
    asm("cvt.rn.bf16x2.f32 %0, %1, %2;" : "=r"(h) : "f"(b), "f"(a));  // low=a
    float ra = a - __uint_as_float(h << 16);
    float rb = b - __uint_as_float(h & 0xffff0000u);
    uint32_t l;
    asm("cvt.rn.bf16x2.f32 %0, %1, %2;" : "=r"(l) : "f"(rb), "f"(ra));
    hi = h; lo = l;
}

__device__ __forceinline__ void mma16816(float* c, const uint32_t* a,
                                         uint32_t b0, uint32_t b1) {
    asm volatile(
        "mma.sync.aligned.m16n8k16.row.col.f32.bf16.bf16.f32 "
        "{%0,%1,%2,%3}, {%4,%5,%6,%7}, {%8,%9}, {%0,%1,%2,%3};"
        : "+f"(c[0]), "+f"(c[1]), "+f"(c[2]), "+f"(c[3])
        : "r"(a[0]), "r"(a[1]), "r"(a[2]), "r"(a[3]), "r"(b0), "r"(b1));
}

// channel -> input pointer selection (folds at compile time per k-step)
__device__ __forceinline__ float2 in_ld(const float* xd, const float* xs,
                                        const float* eap, int c) {
    if (c < HID) return *(const float2*)(xd + c);
    else if (c < 2 * HID) return *(const float2*)(xs + (c - HID));
    else return *(const float2*)(eap + (c - 2 * HID));
}

// ------------------------------ zero kernels -------------------------------
__global__ void zero_m_kernel() {
    int t = blockIdx.x * blockDim.x + threadIdx.x;
    if (t < N_NODES * HID) g_m[t] = 0.f;
}
__global__ void zero_s2s_state_kernel() {
    int t = blockIdx.x * blockDim.x + threadIdx.x;
    if (t < NUM_GRAPHS * HID) { g_qh[t] = 0.f; g_qc[t] = 0.f; }
    if (t < NUM_GRAPHS * 2 * HID) g_qstar[t] = 0.f;
}

// ------------------------------- embedding ---------------------------------
__global__ void embed_kernel(const float* __restrict__ xf,
                             const float* __restrict__ W,
                             const float* __restrict__ b) {
    int t = blockIdx.x * blockDim.x + threadIdx.x;
    if (t >= N_NODES * HID) return;
    int v = t >> 6, o = t & 63;
    const float* xr = xf + v * NODE_DIM;
    float acc = b[o];
#pragma unroll
    for (int c = 0; c < NODE_DIM; c++) acc += xr[c] * W[c * HID + o];
    g_x[t] = acc;
}

// ---------------------- edge message MLP on mma.sync -----------------------
#define KP1 152
#define KP2 136
#define SW1H 0                          // [128][KP1] bf16
#define SW1L (SW1H + 128 * KP1 * 2)
#define SW2H (SW1L + 128 * KP1 * 2)     // [64][KP2] bf16
#define SW2L (SW2H + 64 * KP2 * 2)
#define SB1  (SW2L + 64 * KP2 * 2)      // 128 f32
#define SB2  (SB1 + 512)                // 64 f32
#define EK_WARPS 12
#define EK_THREADS (EK_WARPS * 32)
#define EK_SMEM_BYTES (SB2 + 256)       // ~97KB (weights + biases only)

#define N_TILES (N_EDGES / 16)  // 50000

__global__ __launch_bounds__(EK_THREADS, 1)
void edge_msg_kernel(const int* __restrict__ ei, const float* __restrict__ ea,
                     const float* __restrict__ W1, const float* __restrict__ b1,
                     const float* __restrict__ W2, const float* __restrict__ b2) {
    extern __shared__ char sm[];
    int tid = threadIdx.x;
    int lane = tid & 31, wid = tid >> 5;

    for (int idx = tid; idx < IN_DIM * MSG_HID; idx += EK_THREADS) {
        int k = idx >> 7, n = idx & 127;
        float w = W1[idx];
        __nv_bfloat16 h = __float2bfloat16(w);
        float r = w - __bfloat162float(h);
        __nv_bfloat16 l = __float2bfloat16(r);
        ((__nv_bfloat16*)(sm + SW1H))[n * KP1 + k] = h;
        ((__nv_bfloat16*)(sm + SW1L))[n * KP1 + k] = l;
    }
    for (int idx = tid; idx < MSG_HID * HID; idx += EK_THREADS) {
        int k = idx >> 6, n = idx & 63;
        float w = W2[idx];
        __nv_bfloat16 h = __float2bfloat16(w);
        float r = w - __bfloat162float(h);
        __nv_bfloat16 l = __float2bfloat16(r);
        ((__nv_bfloat16*)(sm + SW2H))[n * KP2 + k] = h;
        ((__nv_bfloat16*)(sm + SW2L))[n * KP2 + k] = l;
    }
    if (tid < MSG_HID) ((float*)(sm + SB1))[tid] = b1[tid];
    if (tid < HID) ((float*)(sm + SB2))[tid] = b2[tid];
    __syncthreads();

    const int* src = ei;
    const int* dst = ei + N_EDGES;
    const float* b1s = (const float*)(sm + SB1);
    const float* b2s = (const float*)(sm + SB2);

    int g = lane >> 2, tg = lane & 3;

    for (int tile = blockIdx.x * EK_WARPS + wid; tile < N_TILES;
         tile += gridDim.x * EK_WARPS) {
        int e0 = tile * 16;
        int eA = e0 + g, eB = e0 + g + 8;
        int dA = __ldg(dst + eA), sA = __ldg(src + eA);
        int dB = __ldg(dst + eB), sB = __ldg(src + eB);
        const float* xdA = g_x + dA * HID;
        const float* xsA = g_x + sA * HID;
        const float* xdB = g_x + dB * HID;
        const float* xsB = g_x + sB * HID;
        const float* eaA = ea + eA * EDGE_DIM;
        const float* eaB = ea + eB * EDGE_DIM;

        // ---- layer 1: direct global->register A fragments ----
        float c1[16][4];
#pragma unroll
        for (int nt = 0; nt < 16; nt++)
#pragma unroll
            for (int j = 0; j < 4; j++) c1[nt][j] = 0.f;

#pragma unroll
        for (int ks = 0; ks < 9; ks++) {
            int cA = ks * 16 + tg * 2;
            int cB = cA + 8;
            float2 vA0 = in_ld(xdA, xsA, eaA, cA);   // row g,   k pair cA
            float2 vA1 = in_ld(xdB, xsB, eaB, cA);   // row g+8, k pair cA
            float2 vB0 = in_ld(xdA, xsA, eaA, cB);   // row g,   k pair cB
            float2 vB1 = in_ld(xdB, xsB, eaB, cB);   // row g+8, k pair cB
            uint32_t ah[4], al[4];
            split2(vA0.x, vA0.y, ah[0], al[0]);
            split2(vA1.x, vA1.y, ah[1], al[1]);
            split2(vB0.x, vB0.y, ah[2], al[2]);
            split2(vB1.x, vB1.y, ah[3], al[3]);

            int kb = ks * 32 + tg * 4;
#pragma unroll
            for (int nt = 0; nt < 16; nt++) {
                const char* wrh = sm + SW1H + (nt * 8 + g) * (KP1 * 2) + kb;
                const char* wrl = sm + SW1L + (nt * 8 + g) * (KP1 * 2) + kb;
                uint32_t bh0 = *(const uint32_t*)wrh;
                uint32_t bh1 = *(const uint32_t*)(wrh + 16);
                uint32_t bl0 = *(const uint32_t*)wrl;
                uint32_t bl1 = *(const uint32_t*)(wrl + 16);
                mma16816(c1[nt], ah, bh0, bh1);
                mma16816(c1[nt], ah, bl0, bl1);
                mma16816(c1[nt], al, bh0, bh1);
            }
        }

        // ---- epilogue 1: bias+relu -> layer-2 A fragments (registers) ----
        uint32_t a2h[8][4], a2l[8][4];
#pragma unroll
        for (int nt = 0; nt < 16; nt++) {
            float2 bb = *(const float2*)(b1s + nt * 8 + tg * 2);
            float h0 = fmaxf(c1[nt][0] + bb.x, 0.f);
            float h1 = fmaxf(c1[nt][1] + bb.y, 0.f);
            float h2 = fmaxf(c1[nt][2] + bb.x, 0.f);
            float h3 = fmaxf(c1[nt][3] + bb.y, 0.f);
            uint32_t hiA, loA, hiB, loB;
            split2(h0, h1, hiA, loA);
            split2(h2, h3, hiB, loB);
            int s = nt >> 1;
            if (nt & 1) {
                a2h[s][2] = hiA; a2h[s][3] = hiB;
                a2l[s][2] = loA; a2l[s][3] = loB;
            } else {
                a2h[s][0] = hiA; a2h[s][1] = hiB;
                a2l[s][0] = loA; a2l[s][1] = loB;
            }
        }

        // ---- layer 2 ----
        float c2[8][4];
#pragma unroll
        for (int nt = 0; nt < 8; nt++)
#pragma unroll
            for (int j = 0; j < 4; j++) c2[nt][j] = 0.f;

#pragma unroll
        for (int s = 0; s < 8; s++) {
            int kb = s * 32 + tg * 4;
#pragma unroll
            for (int nt = 0; nt < 8; nt++) {
                const char* wrh = sm + SW2H + (nt * 8 + g) * (KP2 * 2) + kb;
                const char* wrl = sm + SW2L + (nt * 8 + g) * (KP2 * 2) + kb;
                uint32_t bh0 = *(const uint32_t*)wrh;
                uint32_t bh1 = *(const uint32_t*)(wrh + 16);
                uint32_t bl0 = *(const uint32_t*)wrl;
                uint32_t bl1 = *(const uint32_t*)(wrl + 16);
                mma16816(c2[nt], a2h[s], bh0, bh1);
                mma16816(c2[nt], a2h[s], bl0, bl1);
                mma16816(c2[nt], a2l[s], bh0, bh1);
            }
        }

        // ---- scatter-add with bias ----
#pragma unroll
        for (int nt = 0; nt < 8; nt++) {
            float2 bb = *(const float2*)(b2s + nt * 8 + tg * 2);
            int col = nt * 8 + tg * 2;
            atomicAdd(&g_m[dA * HID + col], c2[nt][0] + bb.x);
            atomicAdd(&g_m[dA * HID + col + 1], c2[nt][1] + bb.y);
            atomicAdd(&g_m[dB * HID + col], c2[nt][2] + bb.x);
            atomicAdd(&g_m[dB * HID + col + 1], c2[nt][3] + bb.y);
        }
    }
}

// --------------------------------- GRU -------------------------------------
// 16 warps/CTA. Also zeroes g_m after consuming it (for the next MP round).
#define GK_THREADS 512
#define GK_WARPS 16
#define NPW 4
#define GRU_SMEM_F (64 * 96 * 2 * 2 + 384 + GK_WARPS * NPW * 128 * 2)

__global__ __launch_bounds__(GK_THREADS, 1)
void gru_kernel(const float* __restrict__ Wih, const float* __restrict__ Whh,
                const float* __restrict__ bih, const float* __restrict__ bhh) {
    extern __shared__ float s[];
    float2* WihT2 = (float2*)s;                 // [c(64)][p(96)]
    float2* WhhT2 = WihT2 + 64 * 96;
    float* bihs = (float*)(WhhT2 + 64 * 96);    // 192
    float* bhhs = bihs + 192;                   // 192
    float2* stg = (float2*)(bhhs + 192);        // [warp][NPW][128] dup (m|h)

    int tid = threadIdx.x;
    for (int idx = tid; idx < 64 * 96; idx += GK_THREADS) {
        int c = idx / 96, p = idx % 96;
        WihT2[c * 96 + p] = make_float2(Wih[(2 * p) * HID + c],
                                        Wih[(2 * p + 1) * HID + c]);
        WhhT2[c * 96 + p] = make_float2(Whh[(2 * p) * HID + c],
                                        Whh[(2 * p + 1) * HID + c]);
    }
    for (int idx = tid; idx < 192; idx += GK_THREADS) {
        bihs[idx] = bih[idx];
        bhhs[idx] = bhh[idx];
    }
    __syncthreads();

    int warp = tid >> 5, lane = tid & 31;
    float2* ws = stg + warp * NPW * 128;
    const int ngroups = N_NODES / NPW;  // 12500

    for (int g = blockIdx.x * GK_WARPS + warp; g < ngroups;
         g += gridDim.x * GK_WARPS) {
        int v0 = g * NPW;
#pragma unroll
        for (int n = 0; n < NPW; n++) {
            int v = v0 + n;
            float m0 = g_m[v * HID + lane];
            float m1 = g_m[v * HID + lane + 32];
            float h0 = g_x[v * HID + lane];
            float h1 = g_x[v * HID + lane + 32];
            // zero message buffer for next round (fused zero_m)
            g_m[v * HID + lane] = 0.f;
            g_m[v * HID + lane + 32] = 0.f;
            ws[n * 128 + lane] = make_float2(m0, m0);
            ws[n * 128 + lane + 32] = make_float2(m1, m1);
            ws[n * 128 + 64 + lane] = make_float2(h0, h0);
            ws[n * 128 + 64 + lane + 32] = make_float2(h1, h1);
        }
        __syncwarp();

        unsigned long long ai[NPW][3], ah[NPW][3];
#pragma unroll
        for (int n = 0; n < NPW; n++)
#pragma unroll
            for (int j = 0; j < 3; j++) { ai[n][j] = 0ull; ah[n][j] = 0ull; }

#pragma unroll 2
        for (int c = 0; c < HID; c++) {
            unsigned long long wi0 = ld2u((const float*)(WihT2 + c * 96 + lane));
            unsigned long long wi1 = ld2u((const float*)(WihT2 + c * 96 + lane + 32));
            unsigned long long wi2 = ld2u((const float*)(WihT2 + c * 96 + lane + 64));
            unsigned long long wh0 = ld2u((const float*)(WhhT2 + c * 96 + lane));
            unsigned long long wh1 = ld2u((const float*)(WhhT2 + c * 96 + lane + 32));
            unsigned long long wh2 = ld2u((const float*)(WhhT2 + c * 96 + lane + 64));
#pragma unroll
            for (int n = 0; n < NPW; n++) {
                unsigned long long mv = ld2u((const float*)(ws + n * 128 + c));
                unsigned long long hv = ld2u((const float*)(ws + n * 128 + 64 + c));
                ai[n][0] = fma2(wi0, mv, ai[n][0]);
                ai[n][1] = fma2(wi1, mv, ai[n][1]);
                ai[n][2] = fma2(wi2, mv, ai[n][2]);
                ah[n][0] = fma2(wh0, hv, ah[n][0]);
                ah[n][1] = fma2(wh1, hv, ah[n][1]);
                ah[n][2] = fma2(wh2, hv, ah[n][2]);
            }
        }

        int u0 = 2 * lane;
#pragma unroll
        for (int n = 0; n < NPW; n++) {
            int v = v0 + n;
            float2 ir = unpk(ai[n][0]), hr = unpk(ah[n][0]);
            float2 iz = unpk(ai[n][1]), hz = unpk(ah[n][1]);
            float2 in_ = unpk(ai[n][2]), hn = unpk(ah[n][2]);
            float holdA = ws[n * 128 + 64 + u0].x;
            float holdB = ws[n * 128 + 64 + u0 + 1].x;
            float rA = sigmoidf_(ir.x + bihs[u0] + hr.x + bhhs[u0]);
            float rB = sigmoidf_(ir.y + bihs[u0 + 1] + hr.y + bhhs[u0 + 1]);
            float zA = sigmoidf_(iz.x + bihs[64 + u0] + hz.x + bhhs[64 + u0]);
            float zB = sigmoidf_(iz.y + bihs[64 + u0 + 1] + hz.y + bhhs[64 + u0 + 1]);
            float nA = tanhf(in_.x + bihs[128 + u0] + rA * (hn.x + bhhs[128 + u0]));
            float nB = tanhf(in_.y + bihs[128 + u0 + 1] + rB * (hn.y + bhhs[128 + u0 + 1]));
            float oA = (1.f - zA) * nA + zA * holdA;
            float oB = (1.f - zB) * nB + zB * holdB;
            *(float2*)(g_x + v * HID + u0) = make_float2(oA, oB);
        }
        __syncwarp();
    }
}

// ------------------------------- LSTM cell ---------------------------------
#define LSTM_SMEM_F (256 * 128 + 256 * 64 + 4 * 128 + 4 * 64)

__global__ __launch_bounds__(256, 1)
void lstm_kernel(const float* __restrict__ Wih, const float* __restrict__ Whh,
                 const float* __restrict__ bih, const float* __restrict__ bhh) {
    extern __shared__ float s[];
    float* WihT = s;                   // [c(128)][gate(256)]
    float* WhhT = WihT + 256 * 128;    // [c(64)][gate(256)]
    float* qs_s = WhhT + 256 * 64;     // [4][128]
    float* qh_s = qs_s + 4 * 128;      // [4][64]

    int tid = threadIdx.x;
    for (int idx = tid; idx < 256 * 128; idx += 256) {
        int g = idx >> 7, c = idx & 127;
        WihT[c * 256 + g] = Wih[idx];
    }
    for (int idx = tid; idx < 256 * 64; idx += 256) {
        int g = idx >> 6, c = idx & 63;
        WhhT[c * 256 + g] = Whh[idx];
    }
    int g0 = blockIdx.x * 4;
    for (int idx = tid; idx < 4 * 128; idx += 256)
        qs_s[idx] = g_qstar[g0 * 128 + idx];
    for (int idx = tid; idx < 4 * 64; idx += 256)
        qh_s[idx] = g_qh[g0 * 64 + idx];
    __syncthreads();

    int lg = tid >> 6;
    int u = tid & 63;
    int g = g0 + lg;
    float accI = bih[u] + bhh[u];
    float accF = bih[64 + u] + bhh[64 + u];
    float accG = bih[128 + u] + bhh[128 + u];
    float accO = bih[192 + u] + bhh[192 + u];
    const float* qs = qs_s + lg * 128;
#pragma unroll 4
    for (int c = 0; c < 128; c++) {
        float v = qs[c];
        const float* w = &WihT[c * 256];
        accI += v * w[u];
        accF += v * w[64 + u];
        accG += v * w[128 + u];
        accO += v * w[192 + u];
    }
    const float* qh = qh_s + lg * 64;
#pragma unroll 4
    for (int c = 0; c < 64; c++) {
        float v = qh[c];
        const float* w = &WhhT[c * 256];
        accI += v * w[u];
        accF += v * w[64 + u];
        accG += v * w[128 + u];
        accO += v * w[192 + u];
    }
    float i_ = sigmoidf_(accI), f_ = sigmoidf_(accF);
    float gg = tanhf(accG), o_ = sigmoidf_(accO);
    float c_new = f_ * g_qc[g * 64 + u] + i_ * gg;
    float h_new = o_ * tanhf(c_new);
    g_qc[g * 64 + u] = c_new;
    g_qh[g * 64 + u] = h_new;
}

// ---------------- fused per-graph Set2Set attention step -------------------
__device__ __forceinline__ int lower_bound_i(const int* b, int n, int key) {
    int lo = 0, hi = n;
    while (lo < hi) {
        int m = (lo + hi) >> 1;
        if (__ldg(b + m) < key) lo = m + 1; else hi = m;
    }
    return lo;
}

__global__ __launch_bounds__(256, 4)
void attn_s2s_kernel(const int* __restrict__ batch) {
    __shared__ float qh_s[HID];
    __shared__ float rv[HID];
    __shared__ float red[8];
    __shared__ float emax_s, asum_s;
    __shared__ int s0_s, s1_s;

    int g = blockIdx.x;
    int tid = threadIdx.x;
    int warp = tid >> 5, lane = tid & 31;

    if (tid == 0) {
        s0_s = lower_bound_i(batch, N_NODES, g);
        s1_s = lower_bound_i(batch, N_NODES, g + 1);
        asum_s = 0.f;
    }
    if (tid < HID) { qh_s[tid] = g_qh[g * HID + tid]; rv[tid] = 0.f; }
    __syncthreads();
    int s0 = s0_s, s1 = s1_s;

    float wmax = -3.4e38f;
    for (int v = s0 + warp; v < s1; v += 8) {
        float p = g_x[v * HID + lane] * qh_s[lane] +
                  g_x[v * HID + lane + 32] * qh_s[lane + 32];
#pragma unroll
        for (int o = 16; o; o >>= 1) p += __shfl_down_sync(0xffffffffu, p, o);
        p = __shfl_sync(0xffffffffu, p, 0);
        if (lane == 0) g_e[v] = p;
        wmax = fmaxf(wmax, p);
    }
    if (lane == 0) red[warp] = wmax;
    __syncthreads();
    if (tid == 0) {
        float m = red[0];
#pragma unroll
        for (int w = 1; w < 8; w++) m = fmaxf(m, red[w]);
        emax_s = m;
    }
    __syncthreads();
    float emax = emax_s;

    float asl = 0.f, r0 = 0.f, r1 = 0.f;
    for (int v = s0 + warp; v < s1; v += 8) {
        float a = expf(g_e[v] - emax);
        asl += a;
        r0 += a * g_x[v * HID + lane];
        r1 += a * g_x[v * HID + lane + 32];
    }
    if (lane == 0 && asl != 0.f) atomicAdd(&asum_s, asl);
    atomicAdd(&rv[lane], r0);
    atomicAdd(&rv[lane + 32], r1);
    __syncthreads();

    if (tid < HID) {
        float denom = asum_s;
        float rval = (s1 > s0) ? rv[tid] / denom : 0.f;
        g_qstar[g * 2 * HID + tid] = qh_s[tid];
        g_qstar[g * 2 * HID + HID + tid] = rval;
    }
}

// ------------------------------- regressor ---------------------------------
__global__ void reg_kernel(const float* __restrict__ W1,
                           const float* __restrict__ b1,
                           const float* __restrict__ W2,
                           const float* __restrict__ b2,
                           float* __restrict__ out) {
    __shared__ float qs[128];
    __shared__ float red[64];
    int g = blockIdx.x;
    int u = threadIdx.x;  // 64 threads
    qs[u] = g_qstar[g * 128 + u];
    qs[u + 64] = g_qstar[g * 128 + u + 64];
    __syncthreads();
    float acc = b1[u];
#pragma unroll 4
    for (int c = 0; c < 128; c++) acc += qs[c] * W1[c * HID + u];
    red[u] = fmaxf(acc, 0.f) * W2[u];
    __syncthreads();
    for (int sft = 32; sft; sft >>= 1) {
        if (u < sft) red[u] += red[u + sft];
        __syncthreads();
    }
    if (u == 0) out[g] = red[0] + b2[0];
}

// ------------------------------ host driver --------------------------------
extern "C" void kernel_launch(void* const* d_in, const int* in_sizes, int n_in,
                              void* d_out, int out_size) {
    const float* x_feat     = (const float*)d_in[0];
    const int*   edge_index = (const int*)d_in[1];
    const float* edge_attr  = (const float*)d_in[2];
    const int*   batch      = (const int*)d_in[3];
    const float* W_emb = (const float*)d_in[4];
    const float* b_emb = (const float*)d_in[5];
    const float* W_m1  = (const float*)d_in[6];
    const float* b_m1  = (const float*)d_in[7];
    const float* W_m2  = (const float*)d_in[8];
    const float* b_m2  = (const float*)d_in[9];
    const float* gWih  = (const float*)d_in[10];
    const float* gWhh  = (const float*)d_in[11];
    const float* gbih  = (const float*)d_in[12];
    const float* gbhh  = (const float*)d_in[13];
    const float* lWih  = (const float*)d_in[14];
    const float* lWhh  = (const float*)d_in[15];
    const float* lbih  = (const float*)d_in[16];
    const float* lbhh  = (const float*)d_in[17];
    const float* Wr1   = (const float*)d_in[18];
    const float* br1   = (const float*)d_in[19];
    const float* Wr2   = (const float*)d_in[20];
    const float* br2   = (const float*)d_in[21];
    float* out = (float*)d_out;

    const int gru_smem  = GRU_SMEM_F * (int)sizeof(float);
    const int lstm_smem = LSTM_SMEM_F * (int)sizeof(float);
    cudaFuncSetAttribute(edge_msg_kernel,
                         cudaFuncAttributeMaxDynamicSharedMemorySize, EK_SMEM_BYTES);
    cudaFuncSetAttribute(gru_kernel,
                         cudaFuncAttributeMaxDynamicSharedMemorySize, gru_smem);
    cudaFuncSetAttribute(lstm_kernel,
                         cudaFuncAttributeMaxDynamicSharedMemorySize, lstm_smem);

    // 1. node embedding + initial g_m clear (later rounds fused into GRU)
    embed_kernel<<<(N_NODES * HID + 255) / 256, 256>>>(x_feat, W_emb, b_emb);
    zero_m_kernel<<<(N_NODES * HID + 255) / 256, 256>>>();

    // 2. message passing rounds
    for (int r = 0; r < NUM_MP; r++) {
        edge_msg_kernel<<<148, EK_THREADS, EK_SMEM_BYTES>>>(edge_index, edge_attr,
                                                            W_m1, b_m1, W_m2, b_m2);
        gru_kernel<<<148, GK_THREADS, gru_smem>>>(gWih, gWhh, gbih, gbhh);
    }

    // 3. Set2Set — 2 launches per step
    zero_s2s_state_kernel<<<(NUM_GRAPHS * 2 * HID + 255) / 256, 256>>>();
    for (int s = 0; s < S2S_STEPS; s++) {
        lstm_kernel<<<NUM_GRAPHS / 4, 256, lstm_smem>>>(lWih, lWhh, lbih, lbhh);
        attn_s2s_kernel<<<NUM_GRAPHS, 256>>>(batch);
    }

    // 4. regressor
    reg_kernel<<<NUM_GRAPHS, 64>>>(Wr1, br1, Wr2, br2, out);
    (void)in_sizes; (void)n_in; (void)out_size;
}

// round 17
// speedup vs baseline: 2.6504x; 1.0553x over previous
#include <cuda_runtime.h>
#include <cuda_bf16.h>
#include <cstdint>

// ---------------------------------------------------------------------------
// MPNN forward, graph-capturable, allocation-free.
// R17: edge MLP mma.sync with fragment-ready weight layout (1 LDS.64 per
// B operand) + red.global.add.v2.f32 scatter. GRU 16w + fused zero;
// fused Set2Set attention.
// ---------------------------------------------------------------------------

#define N_NODES 50000
#define N_EDGES 800000
#define NODE_DIM 32
#define EDGE_DIM 16
#define HID 64
#define MSG_HID 128
#define NUM_GRAPHS 512
#define NUM_MP 3
#define S2S_STEPS 6
#define IN_DIM (2 * HID + EDGE_DIM)  // 144

// ------------------------- scratch (device globals) ------------------------
__device__ __align__(16) float g_x[N_NODES * HID];
__device__ __align__(16) float g_m[N_NODES * HID];
__device__ float g_qh[NUM_GRAPHS * HID];
__device__ float g_qc[NUM_GRAPHS * HID];
__device__ float g_qstar[NUM_GRAPHS * 2 * HID];
__device__ float g_e[N_NODES];

__device__ __forceinline__ float sigmoidf_(float x) { return 1.f / (1.f + expf(-x)); }

// ----------------------- packed f32x2 helpers (GRU) ------------------------
__device__ __forceinline__ unsigned long long fma2(unsigned long long a,
                                                   unsigned long long b,
                                                   unsigned long long c) {
    unsigned long long d;
    asm("fma.rn.f32x2 %0, %1, %2, %3;" : "=l"(d) : "l"(a), "l"(b), "l"(c));
    return d;
}
__device__ __forceinline__ float2 unpk(unsigned long long v) {
    float lo, hi;
    asm("mov.b64 {%0, %1}, %2;" : "=f"(lo), "=f"(hi) : "l"(v));
    return make_float2(lo, hi);
}
__device__ __forceinline__ unsigned long long ld2u(const float* p) {
    return *(const unsigned long long*)p;
}

// --------------------------- mma.sync primitives ---------------------------
__device__ __forceinline__ void split2(float a, float b, uint32_t& hi, uint32_t& lo) {
    uint32_t h;
    asm("cvt.rn.bf16x2.f32 %0, %1, %2;" : "=r"(h) : "f"(b), "f"(a));  // low=a
    float ra = a - __uint_as_float(h << 16);
    float rb = b - __uint_as_float(h & 0xffff0000u);
    uint32_t l;
    asm("cvt.rn.bf16x2.f32 %0, %1, %2;" : "=r"(l) : "f"(rb), "f"(ra));
    hi = h; lo = l;
}

__device__ __forceinline__ void mma16816(float* c, const uint32_t* a,
                                         uint32_t b0, uint32_t b1) {
    asm volatile(
        "mma.sync.aligned.m16n8k16.row.col.f32.bf16.bf16.f32 "
        "{%0,%1,%2,%3}, {%4,%5,%6,%7}, {%8,%9}, {%0,%1,%2,%3};"
        : "+f"(c[0]), "+f"(c[1]), "+f"(c[2]), "+f"(c[3])
        : "r"(a[0]), "r"(a[1]), "r"(a[2]), "r"(a[3]), "r"(b0), "r"(b1));
}

__device__ __forceinline__ void red2(float* p, float v0, float v1) {
    asm volatile("red.global.add.v2.f32 [%0], {%1, %2};"
                 :: "l"(p), "f"(v0), "f"(v1) : "memory");
}

// channel -> input pointer selection (folds at compile time per k-step)
__device__ __forceinline__ float2 in_ld(const float* xd, const float* xs,
                                        const float* eap, int c) {
    if (c < HID) return *(const float2*)(xd + c);
    else if (c < 2 * HID) return *(const float2*)(xs + (c - HID));
    else return *(const float2*)(eap + (c - 2 * HID));
}

// ------------------------------ zero kernels -------------------------------
__global__ void zero_m_kernel() {
    int t = blockIdx.x * blockDim.x + threadIdx.x;
    if (t < N_NODES * HID) g_m[t] = 0.f;
}
__global__ void zero_s2s_state_kernel() {
    int t = blockIdx.x * blockDim.x + threadIdx.x;
    if (t < NUM_GRAPHS * HID) { g_qh[t] = 0.f; g_qc[t] = 0.f; }
    if (t < NUM_GRAPHS * 2 * HID) g_qstar[t] = 0.f;
}

// ------------------------------- embedding ---------------------------------
__global__ void embed_kernel(const float* __restrict__ xf,
                             const float* __restrict__ W,
                             const float* __restrict__ b) {
    int t = blockIdx.x * blockDim.x + threadIdx.x;
    if (t >= N_NODES * HID) return;
    int v = t >> 6, o = t & 63;
    const float* xr = xf + v * NODE_DIM;
    float acc = b[o];
#pragma unroll
    for (int c = 0; c < NODE_DIM; c++) acc += xr[c] * W[c * HID + o];
    g_x[t] = acc;
}

// ---------------------- edge message MLP on mma.sync -----------------------
// Fragment-ready smem weight layout:
//   F1h/F1l: uint2[9][16][8][4]  (ks, nt, g, tg) -> (b0, b1)   36864B each
//   F2h/F2l: uint2[8][8][8][4]                                 16384B each
#define SF1H 0
#define SF1L (SF1H + 9 * 16 * 8 * 4 * 8)    // 36864
#define SF2H (SF1L + 9 * 16 * 8 * 4 * 8)    // 73728
#define SF2L (SF2H + 8 * 8 * 8 * 4 * 8)     // 90112
#define SB1  (SF2L + 8 * 8 * 8 * 4 * 8)     // 106496
#define SB2  (SB1 + 512)
#define EK_WARPS 12
#define EK_THREADS (EK_WARPS * 32)
#define EK_SMEM_BYTES (SB2 + 256)           // 107264

#define N_TILES (N_EDGES / 16)  // 50000

__global__ __launch_bounds__(EK_THREADS, 1)
void edge_msg_kernel(const int* __restrict__ ei, const float* __restrict__ ea,
                     const float* __restrict__ W1, const float* __restrict__ b1,
                     const float* __restrict__ W2, const float* __restrict__ b2) {
    extern __shared__ char sm[];
    int tid = threadIdx.x;
    int lane = tid & 31, wid = tid >> 5;

    // build fragment-ready weights: layer 1 (4608 fragments)
    for (int idx = tid; idx < 9 * 16 * 8 * 4; idx += EK_THREADS) {
        int tg = idx & 3, gg = (idx >> 2) & 7, nt = (idx >> 5) & 15, ks = idx >> 9;
        int n = nt * 8 + gg;
        int k0 = ks * 16 + tg * 2;
        float w00 = W1[k0 * MSG_HID + n];
        float w01 = W1[(k0 + 1) * MSG_HID + n];
        float w10 = W1[(k0 + 8) * MSG_HID + n];
        float w11 = W1[(k0 + 9) * MSG_HID + n];
        uint32_t h0, l0, h1, l1;
        split2(w00, w01, h0, l0);
        split2(w10, w11, h1, l1);
        ((uint2*)(sm + SF1H))[idx] = make_uint2(h0, h1);
        ((uint2*)(sm + SF1L))[idx] = make_uint2(l0, l1);
    }
    // layer 2 (2048 fragments)
    for (int idx = tid; idx < 8 * 8 * 8 * 4; idx += EK_THREADS) {
        int tg = idx & 3, gg = (idx >> 2) & 7, nt = (idx >> 5) & 7, ks = idx >> 8;
        int n = nt * 8 + gg;
        int k0 = ks * 16 + tg * 2;
        float w00 = W2[k0 * HID + n];
        float w01 = W2[(k0 + 1) * HID + n];
        float w10 = W2[(k0 + 8) * HID + n];
        float w11 = W2[(k0 + 9) * HID + n];
        uint32_t h0, l0, h1, l1;
        split2(w00, w01, h0, l0);
        split2(w10, w11, h1, l1);
        ((uint2*)(sm + SF2H))[idx] = make_uint2(h0, h1);
        ((uint2*)(sm + SF2L))[idx] = make_uint2(l0, l1);
    }
    if (tid < MSG_HID) ((float*)(sm + SB1))[tid] = b1[tid];
    if (tid < HID) ((float*)(sm + SB2))[tid] = b2[tid];
    __syncthreads();

    const int* src = ei;
    const int* dst = ei + N_EDGES;
    const float* b1s = (const float*)(sm + SB1);
    const float* b2s = (const float*)(sm + SB2);

    int g = lane >> 2, tg = lane & 3;
    // per-lane fragment pointers (lane-fixed part of the index)
    const uint2* F1h = (const uint2*)(sm + SF1H) + g * 4 + tg;
    const uint2* F1l = (const uint2*)(sm + SF1L) + g * 4 + tg;
    const uint2* F2h = (const uint2*)(sm + SF2H) + g * 4 + tg;
    const uint2* F2l = (const uint2*)(sm + SF2L) + g * 4 + tg;

    for (int tile = blockIdx.x * EK_WARPS + wid; tile < N_TILES;
         tile += gridDim.x * EK_WARPS) {
        int e0 = tile * 16;
        int eA = e0 + g, eB = e0 + g + 8;
        int dA = __ldg(dst + eA), sA = __ldg(src + eA);
        int dB = __ldg(dst + eB), sB = __ldg(src + eB);
        const float* xdA = g_x + dA * HID;
        const float* xsA = g_x + sA * HID;
        const float* xdB = g_x + dB * HID;
        const float* xsB = g_x + sB * HID;
        const float* eaA = ea + eA * EDGE_DIM;
        const float* eaB = ea + eB * EDGE_DIM;

        // ---- layer 1: direct global->register A fragments ----
        float c1[16][4];
#pragma unroll
        for (int nt = 0; nt < 16; nt++)
#pragma unroll
            for (int j = 0; j < 4; j++) c1[nt][j] = 0.f;

#pragma unroll
        for (int ks = 0; ks < 9; ks++) {
            int cA = ks * 16 + tg * 2;
            int cB = cA + 8;
            float2 vA0 = in_ld(xdA, xsA, eaA, cA);
            float2 vA1 = in_ld(xdB, xsB, eaB, cA);
            float2 vB0 = in_ld(xdA, xsA, eaA, cB);
            float2 vB1 = in_ld(xdB, xsB, eaB, cB);
            uint32_t ah[4], al[4];
            split2(vA0.x, vA0.y, ah[0], al[0]);
            split2(vA1.x, vA1.y, ah[1], al[1]);
            split2(vB0.x, vB0.y, ah[2], al[2]);
            split2(vB1.x, vB1.y, ah[3], al[3]);

            const uint2* fh = F1h + ks * (16 * 32);
            const uint2* fl = F1l + ks * (16 * 32);
#pragma unroll
            for (int nt = 0; nt < 16; nt++) {
                uint2 wh = fh[nt * 32];
                uint2 wl = fl[nt * 32];
                mma16816(c1[nt], ah, wh.x, wh.y);
                mma16816(c1[nt], ah, wl.x, wl.y);
                mma16816(c1[nt], al, wh.x, wh.y);
            }
        }

        // ---- epilogue 1: bias+relu -> layer-2 A fragments (registers) ----
        uint32_t a2h[8][4], a2l[8][4];
#pragma unroll
        for (int nt = 0; nt < 16; nt++) {
            float2 bb = *(const float2*)(b1s + nt * 8 + tg * 2);
            float h0 = fmaxf(c1[nt][0] + bb.x, 0.f);
            float h1 = fmaxf(c1[nt][1] + bb.y, 0.f);
            float h2 = fmaxf(c1[nt][2] + bb.x, 0.f);
            float h3 = fmaxf(c1[nt][3] + bb.y, 0.f);
            uint32_t hiA, loA, hiB, loB;
            split2(h0, h1, hiA, loA);
            split2(h2, h3, hiB, loB);
            int s = nt >> 1;
            if (nt & 1) {
                a2h[s][2] = hiA; a2h[s][3] = hiB;
                a2l[s][2] = loA; a2l[s][3] = loB;
            } else {
                a2h[s][0] = hiA; a2h[s][1] = hiB;
                a2l[s][0] = loA; a2l[s][1] = loB;
            }
        }

        // ---- layer 2 ----
        float c2[8][4];
#pragma unroll
        for (int nt = 0; nt < 8; nt++)
#pragma unroll
            for (int j = 0; j < 4; j++) c2[nt][j] = 0.f;

#pragma unroll
        for (int s = 0; s < 8; s++) {
            const uint2* fh = F2h + s * (8 * 32);
            const uint2* fl = F2l + s * (8 * 32);
#pragma unroll
            for (int nt = 0; nt < 8; nt++) {
                uint2 wh = fh[nt * 32];
                uint2 wl = fl[nt * 32];
                mma16816(c2[nt], a2h[s], wh.x, wh.y);
                mma16816(c2[nt], a2h[s], wl.x, wl.y);
                mma16816(c2[nt], a2l[s], wh.x, wh.y);
            }
        }

        // ---- scatter-add with bias (vector red) ----
#pragma unroll
        for (int nt = 0; nt < 8; nt++) {
            float2 bb = *(const float2*)(b2s + nt * 8 + tg * 2);
            int col = nt * 8 + tg * 2;
            red2(&g_m[dA * HID + col], c2[nt][0] + bb.x, c2[nt][1] + bb.y);
            red2(&g_m[dB * HID + col], c2[nt][2] + bb.x, c2[nt][3] + bb.y);
        }
    }
}

// --------------------------------- GRU -------------------------------------
// 16 warps/CTA; zeroes g_m after consuming it.
#define GK_THREADS 512
#define GK_WARPS 16
#define NPW 4
#define GRU_SMEM_F (64 * 96 * 2 * 2 + 384 + GK_WARPS * NPW * 128 * 2)

__global__ __launch_bounds__(GK_THREADS, 1)
void gru_kernel(const float* __restrict__ Wih, const float* __restrict__ Whh,
                const float* __restrict__ bih, const float* __restrict__ bhh) {
    extern __shared__ float s[];
    float2* WihT2 = (float2*)s;                 // [c(64)][p(96)]
    float2* WhhT2 = WihT2 + 64 * 96;
    float* bihs = (float*)(WhhT2 + 64 * 96);    // 192
    float* bhhs = bihs + 192;                   // 192
    float2* stg = (float2*)(bhhs + 192);        // [warp][NPW][128] dup (m|h)

    int tid = threadIdx.x;
    for (int idx = tid; idx < 64 * 96; idx += GK_THREADS) {
        int c = idx / 96, p = idx % 96;
        WihT2[c * 96 + p] = make_float2(Wih[(2 * p) * HID + c],
                                        Wih[(2 * p + 1) * HID + c]);
        WhhT2[c * 96 + p] = make_float2(Whh[(2 * p) * HID + c],
                                        Whh[(2 * p + 1) * HID + c]);
    }
    for (int idx = tid; idx < 192; idx += GK_THREADS) {
        bihs[idx] = bih[idx];
        bhhs[idx] = bhh[idx];
    }
    __syncthreads();

    int warp = tid >> 5, lane = tid & 31;
    float2* ws = stg + warp * NPW * 128;
    const int ngroups = N_NODES / NPW;  // 12500

    for (int g = blockIdx.x * GK_WARPS + warp; g < ngroups;
         g += gridDim.x * GK_WARPS) {
        int v0 = g * NPW;
#pragma unroll
        for (int n = 0; n < NPW; n++) {
            int v = v0 + n;
            float m0 = g_m[v * HID + lane];
            float m1 = g_m[v * HID + lane + 32];
            float h0 = g_x[v * HID + lane];
            float h1 = g_x[v * HID + lane + 32];
            g_m[v * HID + lane] = 0.f;
            g_m[v * HID + lane + 32] = 0.f;
            ws[n * 128 + lane] = make_float2(m0, m0);
            ws[n * 128 + lane + 32] = make_float2(m1, m1);
            ws[n * 128 + 64 + lane] = make_float2(h0, h0);
            ws[n * 128 + 64 + lane + 32] = make_float2(h1, h1);
        }
        __syncwarp();

        unsigned long long ai[NPW][3], ah[NPW][3];
#pragma unroll
        for (int n = 0; n < NPW; n++)
#pragma unroll
            for (int j = 0; j < 3; j++) { ai[n][j] = 0ull; ah[n][j] = 0ull; }

#pragma unroll 2
        for (int c = 0; c < HID; c++) {
            unsigned long long wi0 = ld2u((const float*)(WihT2 + c * 96 + lane));
            unsigned long long wi1 = ld2u((const float*)(WihT2 + c * 96 + lane + 32));
            unsigned long long wi2 = ld2u((const float*)(WihT2 + c * 96 + lane + 64));
            unsigned long long wh0 = ld2u((const float*)(WhhT2 + c * 96 + lane));
            unsigned long long wh1 = ld2u((const float*)(WhhT2 + c * 96 + lane + 32));
            unsigned long long wh2 = ld2u((const float*)(WhhT2 + c * 96 + lane + 64));
#pragma unroll
            for (int n = 0; n < NPW; n++) {
                unsigned long long mv = ld2u((const float*)(ws + n * 128 + c));
                unsigned long long hv = ld2u((const float*)(ws + n * 128 + 64 + c));
                ai[n][0] = fma2(wi0, mv, ai[n][0]);
                ai[n][1] = fma2(wi1, mv, ai[n][1]);
                ai[n][2] = fma2(wi2, mv, ai[n][2]);
                ah[n][0] = fma2(wh0, hv, ah[n][0]);
                ah[n][1] = fma2(wh1, hv, ah[n][1]);
                ah[n][2] = fma2(wh2, hv, ah[n][2]);
            }
        }

        int u0 = 2 * lane;
#pragma unroll
        for (int n = 0; n < NPW; n++) {
            int v = v0 + n;
            float2 ir = unpk(ai[n][0]), hr = unpk(ah[n][0]);
            float2 iz = unpk(ai[n][1]), hz = unpk(ah[n][1]);
            float2 in_ = unpk(ai[n][2]), hn = unpk(ah[n][2]);
            float holdA = ws[n * 128 + 64 + u0].x;
            float holdB = ws[n * 128 + 64 + u0 + 1].x;
            float rA = sigmoidf_(ir.x + bihs[u0] + hr.x + bhhs[u0]);
            float rB = sigmoidf_(ir.y + bihs[u0 + 1] + hr.y + bhhs[u0 + 1]);
            float zA = sigmoidf_(iz.x + bihs[64 + u0] + hz.x + bhhs[64 + u0]);
            float zB = sigmoidf_(iz.y + bihs[64 + u0 + 1] + hz.y + bhhs[64 + u0 + 1]);
            float nA = tanhf(in_.x + bihs[128 + u0] + rA * (hn.x + bhhs[128 + u0]));
            float nB = tanhf(in_.y + bihs[128 + u0 + 1] + rB * (hn.y + bhhs[128 + u0 + 1]));
            float oA = (1.f - zA) * nA + zA * holdA;
            float oB = (1.f - zB) * nB + zB * holdB;
            *(float2*)(g_x + v * HID + u0) = make_float2(oA, oB);
        }
        __syncwarp();
    }
}

// ------------------------------- LSTM cell ---------------------------------
#define LSTM_SMEM_F (256 * 128 + 256 * 64 + 4 * 128 + 4 * 64)

__global__ __launch_bounds__(256, 1)
void lstm_kernel(const float* __restrict__ Wih, const float* __restrict__ Whh,
                 const float* __restrict__ bih, const float* __restrict__ bhh) {
    extern __shared__ float s[];
    float* WihT = s;                   // [c(128)][gate(256)]
    float* WhhT = WihT + 256 * 128;    // [c(64)][gate(256)]
    float* qs_s = WhhT + 256 * 64;     // [4][128]
    float* qh_s = qs_s + 4 * 128;      // [4][64]

    int tid = threadIdx.x;
    for (int idx = tid; idx < 256 * 128; idx += 256) {
        int g = idx >> 7, c = idx & 127;
        WihT[c * 256 + g] = Wih[idx];
    }
    for (int idx = tid; idx < 256 * 64; idx += 256) {
        int g = idx >> 6, c = idx & 63;
        WhhT[c * 256 + g] = Whh[idx];
    }
    int g0 = blockIdx.x * 4;
    for (int idx = tid; idx < 4 * 128; idx += 256)
        qs_s[idx] = g_qstar[g0 * 128 + idx];
    for (int idx = tid; idx < 4 * 64; idx += 256)
        qh_s[idx] = g_qh[g0 * 64 + idx];
    __syncthreads();

    int lg = tid >> 6;
    int u = tid & 63;
    int g = g0 + lg;
    float accI = bih[u] + bhh[u];
    float accF = bih[64 + u] + bhh[64 + u];
    float accG = bih[128 + u] + bhh[128 + u];
    float accO = bih[192 + u] + bhh[192 + u];
    const float* qs = qs_s + lg * 128;
#pragma unroll 4
    for (int c = 0; c < 128; c++) {
        float v = qs[c];
        const float* w = &WihT[c * 256];
        accI += v * w[u];
        accF += v * w[64 + u];
        accG += v * w[128 + u];
        accO += v * w[192 + u];
    }
    const float* qh = qh_s + lg * 64;
#pragma unroll 4
    for (int c = 0; c < 64; c++) {
        float v = qh[c];
        const float* w = &WhhT[c * 256];
        accI += v * w[u];
        accF += v * w[64 + u];
        accG += v * w[128 + u];
        accO += v * w[192 + u];
    }
    float i_ = sigmoidf_(accI), f_ = sigmoidf_(accF);
    float gg = tanhf(accG), o_ = sigmoidf_(accO);
    float c_new = f_ * g_qc[g * 64 + u] + i_ * gg;
    float h_new = o_ * tanhf(c_new);
    g_qc[g * 64 + u] = c_new;
    g_qh[g * 64 + u] = h_new;
}

// ---------------- fused per-graph Set2Set attention step -------------------
__device__ __forceinline__ int lower_bound_i(const int* b, int n, int key) {
    int lo = 0, hi = n;
    while (lo < hi) {
        int m = (lo + hi) >> 1;
        if (__ldg(b + m) < key) lo = m + 1; else hi = m;
    }
    return lo;
}

__global__ __launch_bounds__(256, 4)
void attn_s2s_kernel(const int* __restrict__ batch) {
    __shared__ float qh_s[HID];
    __shared__ float rv[HID];
    __shared__ float red[8];
    __shared__ float emax_s, asum_s;
    __shared__ int s0_s, s1_s;

    int g = blockIdx.x;
    int tid = threadIdx.x;
    int warp = tid >> 5, lane = tid & 31;

    if (tid == 0) {
        s0_s = lower_bound_i(batch, N_NODES, g);
        s1_s = lower_bound_i(batch, N_NODES, g + 1);
        asum_s = 0.f;
    }
    if (tid < HID) { qh_s[tid] = g_qh[g * HID + tid]; rv[tid] = 0.f; }
    __syncthreads();
    int s0 = s0_s, s1 = s1_s;

    float wmax = -3.4e38f;
    for (int v = s0 + warp; v < s1; v += 8) {
        float p = g_x[v * HID + lane] * qh_s[lane] +
                  g_x[v * HID + lane + 32] * qh_s[lane + 32];
#pragma unroll
        for (int o = 16; o; o >>= 1) p += __shfl_down_sync(0xffffffffu, p, o);
        p = __shfl_sync(0xffffffffu, p, 0);
        if (lane == 0) g_e[v] = p;
        wmax = fmaxf(wmax, p);
    }
    if (lane == 0) red[warp] = wmax;
    __syncthreads();
    if (tid == 0) {
        float m = red[0];
#pragma unroll
        for (int w = 1; w < 8; w++) m = fmaxf(m, red[w]);
        emax_s = m;
    }
    __syncthreads();
    float emax = emax_s;

    float asl = 0.f, r0 = 0.f, r1 = 0.f;
    for (int v = s0 + warp; v < s1; v += 8) {
        float a = expf(g_e[v] - emax);
        asl += a;
        r0 += a * g_x[v * HID + lane];
        r1 += a * g_x[v * HID + lane + 32];
    }
    if (lane == 0 && asl != 0.f) atomicAdd(&asum_s, asl);
    atomicAdd(&rv[lane], r0);
    atomicAdd(&rv[lane + 32], r1);
    __syncthreads();

    if (tid < HID) {
        float denom = asum_s;
        float rval = (s1 > s0) ? rv[tid] / denom : 0.f;
        g_qstar[g * 2 * HID + tid] = qh_s[tid];
        g_qstar[g * 2 * HID + HID + tid] = rval;
    }
}

// ------------------------------- regressor ---------------------------------
__global__ void reg_kernel(const float* __restrict__ W1,
                           const float* __restrict__ b1,
                           const float* __restrict__ W2,
                           const float* __restrict__ b2,
                           float* __restrict__ out) {
    __shared__ float qs[128];
    __shared__ float red[64];
    int g = blockIdx.x;
    int u = threadIdx.x;  // 64 threads
    qs[u] = g_qstar[g * 128 + u];
    qs[u + 64] = g_qstar[g * 128 + u + 64];
    __syncthreads();
    float acc = b1[u];
#pragma unroll 4
    for (int c = 0; c < 128; c++) acc += qs[c] * W1[c * HID + u];
    red[u] = fmaxf(acc, 0.f) * W2[u];
    __syncthreads();
    for (int sft = 32; sft; sft >>= 1) {
        if (u < sft) red[u] += red[u + sft];
        __syncthreads();
    }
    if (u == 0) out[g] = red[0] + b2[0];
}

// ------------------------------ host driver --------------------------------
extern "C" void kernel_launch(void* const* d_in, const int* in_sizes, int n_in,
                              void* d_out, int out_size) {
    const float* x_feat     = (const float*)d_in[0];
    const int*   edge_index = (const int*)d_in[1];
    const float* edge_attr  = (const float*)d_in[2];
    const int*   batch      = (const int*)d_in[3];
    const float* W_emb = (const float*)d_in[4];
    const float* b_emb = (const float*)d_in[5];
    const float* W_m1  = (const float*)d_in[6];
    const float* b_m1  = (const float*)d_in[7];
    const float* W_m2  = (const float*)d_in[8];
    const float* b_m2  = (const float*)d_in[9];
    const float* gWih  = (const float*)d_in[10];
    const float* gWhh  = (const float*)d_in[11];
    const float* gbih  = (const float*)d_in[12];
    const float* gbhh  = (const float*)d_in[13];
    const float* lWih  = (const float*)d_in[14];
    const float* lWhh  = (const float*)d_in[15];
    const float* lbih  = (const float*)d_in[16];
    const float* lbhh  = (const float*)d_in[17];
    const float* Wr1   = (const float*)d_in[18];
    const float* br1   = (const float*)d_in[19];
    const float* Wr2   = (const float*)d_in[20];
    const float* br2   = (const float*)d_in[21];
    float* out = (float*)d_out;

    const int gru_smem  = GRU_SMEM_F * (int)sizeof(float);
    const int lstm_smem = LSTM_SMEM_F * (int)sizeof(float);
    cudaFuncSetAttribute(edge_msg_kernel,
                         cudaFuncAttributeMaxDynamicSharedMemorySize, EK_SMEM_BYTES);
    cudaFuncSetAttribute(gru_kernel,
                         cudaFuncAttributeMaxDynamicSharedMemorySize, gru_smem);
    cudaFuncSetAttribute(lstm_kernel,
                         cudaFuncAttributeMaxDynamicSharedMemorySize, lstm_smem);

    // 1. node embedding + initial g_m clear
    embed_kernel<<<(N_NODES * HID + 255) / 256, 256>>>(x_feat, W_emb, b_emb);
    zero_m_kernel<<<(N_NODES * HID + 255) / 256, 256>>>();

    // 2. message passing rounds
    for (int r = 0; r < NUM_MP; r++) {
        edge_msg_kernel<<<148, EK_THREADS, EK_SMEM_BYTES>>>(edge_index, edge_attr,
                                                            W_m1, b_m1, W_m2, b_m2);
        gru_kernel<<<148, GK_THREADS, gru_smem>>>(gWih, gWhh, gbih, gbhh);
    }

    // 3. Set2Set — 2 launches per step
    zero_s2s_state_kernel<<<(NUM_GRAPHS * 2 * HID + 255) / 256, 256>>>();
    for (int s = 0; s < S2S_STEPS; s++) {
        lstm_kernel<<<NUM_GRAPHS / 4, 256, lstm_smem>>>(lWih, lWhh, lbih, lbhh);
        attn_s2s_kernel<<<NUM_GRAPHS, 256>>>(batch);
    }

    // 4. regressor
    reg_kernel<<<NUM_GRAPHS, 64>>>(Wr1, br1, Wr2, br2, out);
    (void)in_sizes; (void)n_in; (void)out_size;
}